// round 12
// baseline (speedup 1.0000x reference)
#include <cuda_runtime.h>
#include <cuda_bf16.h>
#include <cstdint>

typedef unsigned int u32;

#define B_ 4
#define H_ 8
#define L_ 8192
#define D_ 64
#define M_ 256
#define BH_ (B_*H_)
#define CH2 64                              // 64 chunks of 128 l-rows
#define NORMV 0.35355339059327373f          // 64^(-1/4)
#define EPSK 1e-6f
#define EPSZ 1e-6f
#define NT 1024

#define PART_SZ (M_*D_ + M_)                // 16640 floats per partial

__device__ __align__(16) float g_part[BH_*CH2*PART_SZ];   // ~136 MB
__device__ __align__(16) float g_kv[BH_*M_*D_];           // tf32-rounded
__device__ __align__(16) float g_ksum[BH_*M_];            // fp32
__device__ __align__(16) u32 g_Pbh[M_*D_/2];              // bf16-hi pairs
__device__ __align__(16) u32 g_Pbl[M_*D_/2];              // bf16-lo pairs

// ---- tf32 / bf16 / mma helpers ----
__device__ __forceinline__ float tf32r(float x) {
    u32 u; asm("cvt.rna.tf32.f32 %0, %1;" : "=r"(u) : "f"(x));
    return __uint_as_float(u);
}
__device__ __forceinline__ u32 f2u(float x) { return __float_as_uint(x); }
__device__ __forceinline__ u32 bpack(__nv_bfloat16 a, __nv_bfloat16 b) {
    unsigned short ua = *(unsigned short*)&a, ub = *(unsigned short*)&b;
    return (u32)ua | ((u32)ub << 16);
}
__device__ __forceinline__ void bsplit2(float a, float b, u32 &hi, u32 &lo) {
    __nv_bfloat16 ha = __float2bfloat16(a), hb = __float2bfloat16(b);
    float ra = a - __bfloat162float(ha);
    float rb = b - __bfloat162float(hb);
    hi = bpack(ha, hb);
    lo = bpack(__float2bfloat16(ra), __float2bfloat16(rb));
}
__device__ __forceinline__ void mma8(float* c, const u32* a, u32 b0, u32 b1) {
    asm volatile(
        "mma.sync.aligned.m16n8k8.row.col.f32.tf32.tf32.f32 "
        "{%0,%1,%2,%3}, {%4,%5,%6,%7}, {%8,%9}, {%0,%1,%2,%3};"
        : "+f"(c[0]), "+f"(c[1]), "+f"(c[2]), "+f"(c[3])
        : "r"(a[0]), "r"(a[1]), "r"(a[2]), "r"(a[3]), "r"(b0), "r"(b1));
}
__device__ __forceinline__ void mma16(float* c, const u32* a, u32 b0, u32 b1) {
    asm volatile(
        "mma.sync.aligned.m16n8k16.row.col.f32.bf16.bf16.f32 "
        "{%0,%1,%2,%3}, {%4,%5,%6,%7}, {%8,%9}, {%0,%1,%2,%3};"
        : "+f"(c[0]), "+f"(c[1]), "+f"(c[2]), "+f"(c[3])
        : "r"(a[0]), "r"(a[1]), "r"(a[2]), "r"(a[3]), "r"(b0), "r"(b1));
}

// ========== prep: P -> bf16 hi/lo split pairs ==========

__global__ void k_prep_P(const float* __restrict__ Pg) {
    int idx = blockIdx.x * 256 + threadIdx.x;   // 8192 pairs
    float x0 = Pg[2*idx], x1 = Pg[2*idx + 1];
    u32 hi, lo;
    bsplit2(x0, x1, hi, lo);
    g_Pbh[idx] = hi;
    g_Pbl[idx] = lo;
}

// ============================ k1: bf16-GEMM1 + tf32-GEMM2 (1024 thr) ============================
#define KHB_W  0
#define KLB_W  4608
#define PHB_W  9216
#define PLB_W  18432
#define QPT_F  0
#define V_F    33792
#define SQN1_F 43008
#define TMP1_F 43136
#define PKS_F  44160
#define K1_FLOATS 45184
#define K1_SMEM (K1_FLOATS*4)
#define BSTR 36
#define QPT_STR 132
#define VSTR 72

__global__ void __launch_bounds__(NT, 1)
k1_mma(const float* __restrict__ kg, const float* __restrict__ vg) {
    extern __shared__ float smf[];
    u32* smw = (u32*)smf;
    const int t = threadIdx.x;
    const int lane = t & 31, w = t >> 5;      // 32 warps
    const int g = lane >> 2, tig = lane & 3;
    const int bh = blockIdx.x >> 6, tile = blockIdx.x & 63;
    const int l0 = tile * 128;
    const size_t gbase = (size_t)bh * L_ * D_;

    // ---- copy P bf16 hi/lo into stride-36 smem ----
    {
        const uint4* sh = (const uint4*)g_Pbh;   // 2048 uint4
        const uint4* sl = (const uint4*)g_Pbl;
#pragma unroll
        for (int i = 0; i < 2; i++) {
            int id = t + i * NT;
            int m = id >> 3, j = id & 7;
            *(uint4*)(smw + PHB_W + m*BSTR + j*4) = sh[id];
            *(uint4*)(smw + PLB_W + m*BSTR + j*4) = sl[id];
        }
    }
    // ---- load k tile (each thread: 1 row, 8 cols), scale, bf16 split, sqn ----
    {
        const int r = t >> 3, c = t & 7;
        const float4* src = (const float4*)(kg + gbase + (size_t)(l0 + r)*D_ + c*8);
        float ss = 0.f;
#pragma unroll
        for (int i = 0; i < 2; i++) {
            float4 x = src[i];
            x.x *= NORMV; x.y *= NORMV; x.z *= NORMV; x.w *= NORMV;
            ss += x.x*x.x + x.y*x.y + x.z*x.z + x.w*x.w;
            u32 h01, l01, h23, l23;
            bsplit2(x.x, x.y, h01, l01);
            bsplit2(x.z, x.w, h23, l23);
            *(uint2*)(smw + KHB_W + r*BSTR + c*4 + 2*i) = make_uint2(h01, h23);
            *(uint2*)(smw + KLB_W + r*BSTR + c*4 + 2*i) = make_uint2(l01, l23);
        }
        smf[TMP1_F + t] = ss;
    }
    __syncthreads();
    if (t < 128) {
        float s = 0.f;
#pragma unroll
        for (int c = 0; c < 8; c++) s += smf[TMP1_F + 8*t + c];
        smf[SQN1_F + t] = 0.5f * s;
    }
    __syncthreads();

    // ---- GEMM1 (bf16 k16): proj[128,256], warp grid 4l x 8n, 32x32/warp ----
    const int lbase = (w & 3) * 32;
    const int n0base = (w >> 2) * 32;
    float acc[2][4][4];
#pragma unroll
    for (int lt = 0; lt < 2; lt++)
#pragma unroll
        for (int nt = 0; nt < 4; nt++)
#pragma unroll
            for (int i = 0; i < 4; i++) acc[lt][nt][i] = 0.f;

#pragma unroll
    for (int ks = 0; ks < 4; ks++) {
        const int k0w = ks * 8;
        u32 ah[2][4], al[2][4];
#pragma unroll
        for (int lt = 0; lt < 2; lt++) {
            const int base = (lbase + lt*16 + g)*BSTR + k0w + tig;
            ah[lt][0] = smw[KHB_W + base];
            ah[lt][1] = smw[KHB_W + base + 8*BSTR];
            ah[lt][2] = smw[KHB_W + base + 4];
            ah[lt][3] = smw[KHB_W + base + 8*BSTR + 4];
            al[lt][0] = smw[KLB_W + base];
            al[lt][1] = smw[KLB_W + base + 8*BSTR];
            al[lt][2] = smw[KLB_W + base + 4];
            al[lt][3] = smw[KLB_W + base + 8*BSTR + 4];
        }
#pragma unroll
        for (int nt = 0; nt < 4; nt++) {
            const int bb = (n0base + nt*8 + g)*BSTR + k0w + tig;
            u32 bh0 = smw[PHB_W + bb];
            u32 bh1 = smw[PHB_W + bb + 4];
            u32 bl0 = smw[PLB_W + bb];
            u32 bl1 = smw[PLB_W + bb + 4];
#pragma unroll
            for (int lt = 0; lt < 2; lt++) {
                mma16(acc[lt][nt], ah[lt], bh0, bh1);
                mma16(acc[lt][nt], ah[lt], bl0, bl1);
                mma16(acc[lt][nt], al[lt], bh0, bh1);
            }
        }
    }
    __syncthreads();   // phase-A operands dead

    // ---- Epilogue 1: exp, tf32 store TRANSPOSED qpT[m][l], ksum partials ----
    {
        float sqa[2][2];
#pragma unroll
        for (int lt = 0; lt < 2; lt++) {
            const int r1 = lbase + lt*16 + g;
            sqa[lt][0] = smf[SQN1_F + r1];
            sqa[lt][1] = smf[SQN1_F + r1 + 8];
        }
#pragma unroll
        for (int nt = 0; nt < 4; nt++) {
            const int n = n0base + nt*8 + 2*tig;
            float cs0 = 0.f, cs1 = 0.f;
#pragma unroll
            for (int lt = 0; lt < 2; lt++) {
                const int r1 = lbase + lt*16 + g;
                const int r2 = r1 + 8;
                float e00 = __expf(acc[lt][nt][0] - sqa[lt][0] + EPSK);
                float e01 = __expf(acc[lt][nt][1] - sqa[lt][0] + EPSK);
                float e10 = __expf(acc[lt][nt][2] - sqa[lt][1] + EPSK);
                float e11 = __expf(acc[lt][nt][3] - sqa[lt][1] + EPSK);
                cs0 += e00 + e10;
                cs1 += e01 + e11;
                smf[QPT_F + n*QPT_STR + r1]     = tf32r(e00);
                smf[QPT_F + (n+1)*QPT_STR + r1] = tf32r(e01);
                smf[QPT_F + n*QPT_STR + r2]     = tf32r(e10);
                smf[QPT_F + (n+1)*QPT_STR + r2] = tf32r(e11);
            }
            cs0 += __shfl_xor_sync(0xffffffffu, cs0, 4);
            cs0 += __shfl_xor_sync(0xffffffffu, cs0, 8);
            cs0 += __shfl_xor_sync(0xffffffffu, cs0, 16);
            cs1 += __shfl_xor_sync(0xffffffffu, cs1, 4);
            cs1 += __shfl_xor_sync(0xffffffffu, cs1, 8);
            cs1 += __shfl_xor_sync(0xffffffffu, cs1, 16);
            if (lane < 4) {
                smf[PKS_F + w*32 + nt*8 + 2*tig]     = cs0;
                smf[PKS_F + w*32 + nt*8 + 2*tig + 1] = cs1;
            }
        }
    }
    // ---- load v tile (tf32-rounded) into stride-72 fp32 smem ----
    {
        const float4* src = (const float4*)(vg + gbase + (size_t)l0*D_);
#pragma unroll
        for (int i = 0; i < 2; i++) {
            int id = t + i * NT;               // 2048 float4
            int l = id >> 4, c4 = id & 15;
            float4 x = src[id];
            x.x = tf32r(x.x); x.y = tf32r(x.y); x.z = tf32r(x.z); x.w = tf32r(x.w);
            *(float4*)(smf + V_F + l*VSTR + c4*4) = x;
        }
    }
    __syncthreads();

    // ---- GEMM2 (tf32): kv_partial[256,64] = qpT @ v; warp grid 16m x 2d ----
    const int m0 = (w & 15) * 16;
    const int colbase = (w >> 4) * 32;
    float acc2[4][4];
#pragma unroll
    for (int nt = 0; nt < 4; nt++)
#pragma unroll
        for (int i = 0; i < 4; i++) acc2[nt][i] = 0.f;

    for (int k8 = 0; k8 < 16; k8++) {
        const int lk = k8 * 8;
        u32 a[4];
        a[0] = f2u(smf[QPT_F + (m0+g)*QPT_STR + lk + tig]);
        a[1] = f2u(smf[QPT_F + (m0+8+g)*QPT_STR + lk + tig]);
        a[2] = f2u(smf[QPT_F + (m0+g)*QPT_STR + lk + tig + 4]);
        a[3] = f2u(smf[QPT_F + (m0+8+g)*QPT_STR + lk + tig + 4]);
#pragma unroll
        for (int nt = 0; nt < 4; nt++) {
            u32 b0 = f2u(smf[V_F + (lk+tig)*VSTR + colbase + nt*8 + g]);
            u32 b1 = f2u(smf[V_F + (lk+tig+4)*VSTR + colbase + nt*8 + g]);
            mma8(acc2[nt], a, b0, b1);
        }
    }

    // ---- write kv partial + ksum partial ----
    float* pb = g_part + (size_t)(bh*CH2 + tile) * PART_SZ;
    {
        const int r1 = m0 + g, r2 = r1 + 8;
#pragma unroll
        for (int nt = 0; nt < 4; nt++) {
            const int d = colbase + nt*8 + 2*tig;
            *(float2*)(pb + r1*D_ + d) = make_float2(acc2[nt][0], acc2[nt][1]);
            *(float2*)(pb + r2*D_ + d) = make_float2(acc2[nt][2], acc2[nt][3]);
        }
    }
    if (t < M_) {
        const int grp = t >> 5, nloc = t & 31;
        float s = smf[PKS_F + (grp*4+0)*32 + nloc]
                + smf[PKS_F + (grp*4+1)*32 + nloc]
                + smf[PKS_F + (grp*4+2)*32 + nloc]
                + smf[PKS_F + (grp*4+3)*32 + nloc];
        pb[M_*D_ + t] = s;
    }
}

// ========== reduce: partials -> ksum fp32, kv tf32-rounded fp32 ==========

__global__ void k_reduce() {
    int idx = blockIdx.x * 256 + threadIdx.x;
    int bh = idx / PART_SZ;
    int r  = idx - bh * PART_SZ;
    const float* p = g_part + (size_t)bh * CH2 * PART_SZ + r;
    float s = 0.f;
#pragma unroll
    for (int c = 0; c < CH2; c++) s += p[(size_t)c * PART_SZ];
    if (r < M_*D_) g_kv[bh*M_*D_ + r] = tf32r(s);
    else           g_ksum[bh*M_ + (r - M_*D_)] = s;
}

// ============================ k2: bf16-GEMM1 + tf32-GEMM2 (1024 thr) ============================
#define QHB_W  0
#define QLB_W  4608
#define PHB2_W 9216
#define PLB2_W 18432
#define QP_F   0
#define KV_F   33280
#define SQN_F  51712
#define KSUM_F 51840
#define ZP_F   52096
#define TMP_F  53120
#define K2_FLOATS 54144
#define K2_SMEM (K2_FLOATS*4)
#define QPSTR 260
#define KVSTR 72

__global__ void __launch_bounds__(NT, 1)
k2_out(const float* __restrict__ qg, float* __restrict__ outg) {
    extern __shared__ float smf[];
    u32* smw = (u32*)smf;
    const int t = threadIdx.x;
    const int lane = t & 31, w = t >> 5;      // 32 warps
    const int g = lane >> 2, tig = lane & 3;
    const int bh = blockIdx.x >> 6, tile = blockIdx.x & 63;
    const int l0 = tile * 128;
    const size_t gbase = (size_t)bh * L_ * D_;

    // ---- copy P bf16 hi/lo ----
    {
        const uint4* sh = (const uint4*)g_Pbh;
        const uint4* sl = (const uint4*)g_Pbl;
#pragma unroll
        for (int i = 0; i < 2; i++) {
            int id = t + i * NT;
            int m = id >> 3, j = id & 7;
            *(uint4*)(smw + PHB2_W + m*BSTR + j*4) = sh[id];
            *(uint4*)(smw + PLB2_W + m*BSTR + j*4) = sl[id];
        }
    }
    // ---- load q tile, scale, bf16 split, sqn partials ----
    {
        const int r = t >> 3, c = t & 7;
        const float4* src = (const float4*)(qg + gbase + (size_t)(l0 + r)*D_ + c*8);
        float ss = 0.f;
#pragma unroll
        for (int i = 0; i < 2; i++) {
            float4 x = src[i];
            x.x *= NORMV; x.y *= NORMV; x.z *= NORMV; x.w *= NORMV;
            ss += x.x*x.x + x.y*x.y + x.z*x.z + x.w*x.w;
            u32 h01, l01, h23, l23;
            bsplit2(x.x, x.y, h01, l01);
            bsplit2(x.z, x.w, h23, l23);
            *(uint2*)(smw + QHB_W + r*BSTR + c*4 + 2*i) = make_uint2(h01, h23);
            *(uint2*)(smw + QLB_W + r*BSTR + c*4 + 2*i) = make_uint2(l01, l23);
        }
        smf[TMP_F + t] = ss;
    }
    if (t < M_) smf[KSUM_F + t] = g_ksum[bh*M_ + t];
    __syncthreads();
    if (t < 128) {
        float s = 0.f;
#pragma unroll
        for (int c = 0; c < 8; c++) s += smf[TMP_F + 8*t + c];
        smf[SQN_F + t] = 0.5f * s;
    }
    __syncthreads();

    // ---- GEMM1 (bf16 k16): proj[128,256], warp grid 4l x 8n ----
    const int lbase = (w & 3) * 32;
    const int n0base = (w >> 2) * 32;
    float acc[2][4][4];
#pragma unroll
    for (int lt = 0; lt < 2; lt++)
#pragma unroll
        for (int nt = 0; nt < 4; nt++)
#pragma unroll
            for (int i = 0; i < 4; i++) acc[lt][nt][i] = 0.f;

#pragma unroll
    for (int ks = 0; ks < 4; ks++) {
        const int k0w = ks * 8;
        u32 ah[2][4], al[2][4];
#pragma unroll
        for (int lt = 0; lt < 2; lt++) {
            const int base = (lbase + lt*16 + g)*BSTR + k0w + tig;
            ah[lt][0] = smw[QHB_W + base];
            ah[lt][1] = smw[QHB_W + base + 8*BSTR];
            ah[lt][2] = smw[QHB_W + base + 4];
            ah[lt][3] = smw[QHB_W + base + 8*BSTR + 4];
            al[lt][0] = smw[QLB_W + base];
            al[lt][1] = smw[QLB_W + base + 8*BSTR];
            al[lt][2] = smw[QLB_W + base + 4];
            al[lt][3] = smw[QLB_W + base + 8*BSTR + 4];
        }
#pragma unroll
        for (int nt = 0; nt < 4; nt++) {
            const int bb = (n0base + nt*8 + g)*BSTR + k0w + tig;
            u32 bh0 = smw[PHB2_W + bb];
            u32 bh1 = smw[PHB2_W + bb + 4];
            u32 bl0 = smw[PLB2_W + bb];
            u32 bl1 = smw[PLB2_W + bb + 4];
#pragma unroll
            for (int lt = 0; lt < 2; lt++) {
                mma16(acc[lt][nt], ah[lt], bh0, bh1);
                mma16(acc[lt][nt], ah[lt], bl0, bl1);
                mma16(acc[lt][nt], al[lt], bh0, bh1);
            }
        }
    }
    __syncthreads();

    // ---- Epilogue 1: exp, z-dot, tf32 round, store q' ----
#pragma unroll
    for (int lt = 0; lt < 2; lt++) {
        const int r1 = lbase + lt*16 + g;
        const int r2 = r1 + 8;
        const float sq1 = smf[SQN_F + r1], sq2 = smf[SQN_F + r2];
        float za1 = 0.f, za2 = 0.f;
#pragma unroll
        for (int nt = 0; nt < 4; nt++) {
            const int n = n0base + nt*8 + 2*tig;
            const float ks0 = smf[KSUM_F + n], ks1 = smf[KSUM_F + n + 1];
            float e00 = __expf(acc[lt][nt][0] - sq1 + EPSK);
            float e01 = __expf(acc[lt][nt][1] - sq1 + EPSK);
            float e10 = __expf(acc[lt][nt][2] - sq2 + EPSK);
            float e11 = __expf(acc[lt][nt][3] - sq2 + EPSK);
            za1 += e00*ks0 + e01*ks1;
            za2 += e10*ks0 + e11*ks1;
            *(float2*)(smf + QP_F + r1*QPSTR + n) = make_float2(tf32r(e00), tf32r(e01));
            *(float2*)(smf + QP_F + r2*QPSTR + n) = make_float2(tf32r(e10), tf32r(e11));
        }
        za1 += __shfl_xor_sync(0xffffffffu, za1, 1);
        za1 += __shfl_xor_sync(0xffffffffu, za1, 2);
        za2 += __shfl_xor_sync(0xffffffffu, za2, 1);
        za2 += __shfl_xor_sync(0xffffffffu, za2, 2);
        if (tig == 0) {
            float* zp = smf + ZP_F + (w >> 2) * 128;
            zp[r1] = za1;
            zp[r2] = za2;
        }
    }
    // ---- load kv (tf32-rounded) into stride-72 smem ----
    {
        const float4* src = (const float4*)(g_kv + (size_t)bh * M_ * D_);
#pragma unroll
        for (int i = 0; i < 4; i++) {
            int id = t + i * NT;               // 4096 float4
            int m = id >> 4, c4 = id & 15;
            *(float4*)(smf + KV_F + m*KVSTR + c4*4) = src[id];
        }
    }
    __syncthreads();

    // ---- GEMM2 (tf32): out[128,64] = q' @ kv; warp grid 8l x 4d ----
    const int r0 = (w & 7) * 16;
    const int colbase = (w >> 3) * 16;
    float acc2[2][4];
#pragma unroll
    for (int nt = 0; nt < 2; nt++)
#pragma unroll
        for (int i = 0; i < 4; i++) acc2[nt][i] = 0.f;

    for (int km = 0; km < 32; km++) {
        const int m0 = km * 8;
        u32 a[4];
        a[0] = f2u(smf[QP_F + (r0+g)*QPSTR + m0 + tig]);
        a[1] = f2u(smf[QP_F + (r0+8+g)*QPSTR + m0 + tig]);
        a[2] = f2u(smf[QP_F + (r0+g)*QPSTR + m0 + tig + 4]);
        a[3] = f2u(smf[QP_F + (r0+8+g)*QPSTR + m0 + tig + 4]);
#pragma unroll
        for (int nt = 0; nt < 2; nt++) {
            u32 b0 = f2u(smf[KV_F + (m0+tig)*KVSTR + colbase + nt*8 + g]);
            u32 b1 = f2u(smf[KV_F + (m0+tig+4)*KVSTR + colbase + nt*8 + g]);
            mma8(acc2[nt], a, b0, b1);
        }
    }

    // ---- Epilogue 2: z from 8 group partials, store ----
    {
        const float* zp = smf + ZP_F;
        const int r1 = r0 + g, r2 = r1 + 8;
        float zs1 = EPSZ, zs2 = EPSZ;
#pragma unroll
        for (int j = 0; j < 8; j++) {
            zs1 += zp[j*128 + r1];
            zs2 += zp[j*128 + r2];
        }
        const float z1 = 1.0f / zs1, z2 = 1.0f / zs2;
        float* o1 = outg + gbase + (size_t)(l0 + r1)*D_ + colbase;
        float* o2 = outg + gbase + (size_t)(l0 + r2)*D_ + colbase;
#pragma unroll
        for (int nt = 0; nt < 2; nt++) {
            const int d = nt*8 + 2*tig;
            *(float2*)(o1 + d) = make_float2(acc2[nt][0]*z1, acc2[nt][1]*z1);
            *(float2*)(o2 + d) = make_float2(acc2[nt][2]*z2, acc2[nt][3]*z2);
        }
    }
}

extern "C" void kernel_launch(void* const* d_in, const int* in_sizes, int n_in,
                              void* d_out, int out_size) {
    (void)in_sizes; (void)n_in; (void)out_size;
    const float* q = (const float*)d_in[0];
    const float* k = (const float*)d_in[1];
    const float* v = (const float*)d_in[2];
    const float* P = (const float*)d_in[3];
    float* out = (float*)d_out;

    cudaFuncSetAttribute(k1_mma, cudaFuncAttributeMaxDynamicSharedMemorySize, K1_SMEM);
    cudaFuncSetAttribute(k2_out, cudaFuncAttributeMaxDynamicSharedMemorySize, K2_SMEM);

    k_prep_P<<<32, 256>>>(P);
    k1_mma<<<BH_*CH2, NT, K1_SMEM>>>(k, v);
    k_reduce<<<(BH_*PART_SZ)/256, 256>>>();
    k2_out<<<BH_*CH2, NT, K2_SMEM>>>(q, out);
}

// round 13
// speedup vs baseline: 1.0349x; 1.0349x over previous
#include <cuda_runtime.h>
#include <cuda_bf16.h>
#include <cstdint>

typedef unsigned int u32;

#define B_ 4
#define H_ 8
#define L_ 8192
#define D_ 64
#define M_ 256
#define BH_ (B_*H_)
#define CH2 64                              // 64 chunks of 128 l-rows
#define NORMV 0.35355339059327373f          // 64^(-1/4)
#define EPSK 1e-6f
#define EPSZ 1e-6f
#define NT 512

#define PART_SZ (M_*D_ + M_)                // 16640 floats per partial

__device__ __align__(16) float g_part[BH_*CH2*PART_SZ];   // ~136 MB
__device__ __align__(16) float g_kv[BH_*M_*D_];           // tf32-rounded
__device__ __align__(16) float g_ksum[BH_*M_];            // fp32
__device__ __align__(16) u32 g_Pbh[M_*D_/2];              // bf16-hi pairs
__device__ __align__(16) u32 g_Pbl[M_*D_/2];              // bf16-lo pairs

// ---- tf32 / bf16 / mma helpers ----
__device__ __forceinline__ float tf32r(float x) {
    u32 u; asm("cvt.rna.tf32.f32 %0, %1;" : "=r"(u) : "f"(x));
    return __uint_as_float(u);
}
__device__ __forceinline__ u32 f2u(float x) { return __float_as_uint(x); }
__device__ __forceinline__ u32 bpack(__nv_bfloat16 a, __nv_bfloat16 b) {
    unsigned short ua = *(unsigned short*)&a, ub = *(unsigned short*)&b;
    return (u32)ua | ((u32)ub << 16);
}
__device__ __forceinline__ void bsplit2(float a, float b, u32 &hi, u32 &lo) {
    __nv_bfloat16 ha = __float2bfloat16(a), hb = __float2bfloat16(b);
    float ra = a - __bfloat162float(ha);
    float rb = b - __bfloat162float(hb);
    hi = bpack(ha, hb);
    lo = bpack(__float2bfloat16(ra), __float2bfloat16(rb));
}
__device__ __forceinline__ void mma8(float* c, const u32* a, u32 b0, u32 b1) {
    asm volatile(
        "mma.sync.aligned.m16n8k8.row.col.f32.tf32.tf32.f32 "
        "{%0,%1,%2,%3}, {%4,%5,%6,%7}, {%8,%9}, {%0,%1,%2,%3};"
        : "+f"(c[0]), "+f"(c[1]), "+f"(c[2]), "+f"(c[3])
        : "r"(a[0]), "r"(a[1]), "r"(a[2]), "r"(a[3]), "r"(b0), "r"(b1));
}
__device__ __forceinline__ void mma16(float* c, const u32* a, u32 b0, u32 b1) {
    asm volatile(
        "mma.sync.aligned.m16n8k16.row.col.f32.bf16.bf16.f32 "
        "{%0,%1,%2,%3}, {%4,%5,%6,%7}, {%8,%9}, {%0,%1,%2,%3};"
        : "+f"(c[0]), "+f"(c[1]), "+f"(c[2]), "+f"(c[3])
        : "r"(a[0]), "r"(a[1]), "r"(a[2]), "r"(a[3]), "r"(b0), "r"(b1));
}
#define LDSM_X4(r0, r1, r2, r3, addr) \
    asm volatile("ldmatrix.sync.aligned.m8n8.x4.shared.b16 {%0,%1,%2,%3}, [%4];" \
        : "=r"(r0), "=r"(r1), "=r"(r2), "=r"(r3) : "r"(addr))

// ========== prep: P -> bf16 hi/lo split pairs ==========

__global__ void k_prep_P(const float* __restrict__ Pg) {
    int idx = blockIdx.x * 256 + threadIdx.x;   // 8192 pairs
    float x0 = Pg[2*idx], x1 = Pg[2*idx + 1];
    u32 hi, lo;
    bsplit2(x0, x1, hi, lo);
    g_Pbh[idx] = hi;
    g_Pbl[idx] = lo;
}

// ============================ k1: bf16-GEMM1 + tf32-GEMM2 ============================
#define KHB_W  0
#define KLB_W  4608
#define PHB_W  9216
#define PLB_W  18432
#define QPT_F  0
#define V_F    33792
#define SQN1_F 43008
#define PKS_F  43136
#define K1_FLOATS 44160
#define K1_SMEM (K1_FLOATS*4)
#define BSTR 36
#define QPT_STR 132
#define VSTR 72

__global__ void __launch_bounds__(NT, 1)
k1_mma(const float* __restrict__ kg, const float* __restrict__ vg) {
    extern __shared__ float smf[];
    u32* smw = (u32*)smf;
    const int t = threadIdx.x;
    const int lane = t & 31, w = t >> 5;      // 16 warps
    const int g = lane >> 2, tig = lane & 3;
    const int bh = blockIdx.x >> 6, tile = blockIdx.x & 63;
    const int l0 = tile * 128;
    const size_t gbase = (size_t)bh * L_ * D_;

    // ---- copy P bf16 hi/lo into stride-36 smem ----
    {
        const uint4* sh = (const uint4*)g_Pbh;   // 2048 uint4
        const uint4* sl = (const uint4*)g_Pbl;
#pragma unroll
        for (int i = 0; i < 4; i++) {
            int id = t + i * NT;
            int m = id >> 3, j = id & 7;
            *(uint4*)(smw + PHB_W + m*BSTR + j*4) = sh[id];
            *(uint4*)(smw + PLB_W + m*BSTR + j*4) = sl[id];
        }
    }
    // ---- load k tile, scale, bf16 split, sqn via shfl ----
    {
        const int r = t >> 2, c0w = (t & 3) * 8;
        const float4* src = (const float4*)(kg + gbase + (size_t)(l0 + r)*D_ + (t & 3)*16);
        float ss = 0.f;
#pragma unroll
        for (int i = 0; i < 4; i++) {
            float4 x = src[i];
            x.x *= NORMV; x.y *= NORMV; x.z *= NORMV; x.w *= NORMV;
            ss += x.x*x.x + x.y*x.y + x.z*x.z + x.w*x.w;
            u32 h01, l01, h23, l23;
            bsplit2(x.x, x.y, h01, l01);
            bsplit2(x.z, x.w, h23, l23);
            *(uint2*)(smw + KHB_W + r*BSTR + c0w + 2*i) = make_uint2(h01, h23);
            *(uint2*)(smw + KLB_W + r*BSTR + c0w + 2*i) = make_uint2(l01, l23);
        }
        ss += __shfl_xor_sync(0xffffffffu, ss, 1);
        ss += __shfl_xor_sync(0xffffffffu, ss, 2);
        if ((lane & 3) == 0) smf[SQN1_F + r] = 0.5f * ss;
    }
    // ---- v tile (tf32-rounded) EARLY: region doesn't alias phase-A operands ----
    {
        const float4* src = (const float4*)(vg + gbase + (size_t)l0*D_);
#pragma unroll
        for (int i = 0; i < 4; i++) {
            int id = t + i * NT;               // 2048 float4
            int l = id >> 4, c4 = id & 15;
            float4 x = src[id];
            x.x = tf32r(x.x); x.y = tf32r(x.y); x.z = tf32r(x.z); x.w = tf32r(x.w);
            *(float4*)(smf + V_F + l*VSTR + c4*4) = x;
        }
    }
    __syncthreads();

    // ---- GEMM1 (bf16 k16, ldmatrix): proj[128,256], warp grid 4x4, 32x64/warp ----
    const int lbase = (w & 3) * 32;
    const int n0base = (w >> 2) * 64;
    // ldmatrix lane addressing (A: lanes 0-7 rows0-7/k0-7, 8-15 rows8-15/k0-7,
    //  16-23 rows0-7/k8-15, 24-31 rows8-15/k8-15;  B: 0-7 n0-7/k0-7, 8-15 n0-7/k8-15,
    //  16-23 n8-15/k0-7, 24-31 n8-15/k8-15)
    const int aRow = (lane & 7) + ((lane >> 3) & 1) * 8;
    const int aCol = ((lane >> 4) & 1) * 16;
    const int bRow = (lane & 7) + ((lane >> 4) & 1) * 8;
    const int bCol = ((lane >> 3) & 1) * 16;
    const u32 aHi0 = (u32)__cvta_generic_to_shared(smw + KHB_W + (lbase + aRow)*BSTR) + aCol;
    const u32 aLo0 = (u32)__cvta_generic_to_shared(smw + KLB_W + (lbase + aRow)*BSTR) + aCol;
    const u32 bHi0 = (u32)__cvta_generic_to_shared(smw + PHB_W + (n0base + bRow)*BSTR) + bCol;
    const u32 bLo0 = (u32)__cvta_generic_to_shared(smw + PLB_W + (n0base + bRow)*BSTR) + bCol;

    float acc[2][8][4];
#pragma unroll
    for (int lt = 0; lt < 2; lt++)
#pragma unroll
        for (int nt = 0; nt < 8; nt++)
#pragma unroll
            for (int i = 0; i < 4; i++) acc[lt][nt][i] = 0.f;

#pragma unroll
    for (int ks = 0; ks < 4; ks++) {
        const u32 off = ks * 32;               // 8 words = 16 bf16 per k-step
        u32 ah[2][4], al[2][4];
        LDSM_X4(ah[0][0], ah[0][1], ah[0][2], ah[0][3], aHi0 + off);
        LDSM_X4(ah[1][0], ah[1][1], ah[1][2], ah[1][3], aHi0 + 2304 + off);
        LDSM_X4(al[0][0], al[0][1], al[0][2], al[0][3], aLo0 + off);
        LDSM_X4(al[1][0], al[1][1], al[1][2], al[1][3], aLo0 + 2304 + off);
#pragma unroll
        for (int p = 0; p < 4; p++) {
            u32 bhv[4], blv[4];
            LDSM_X4(bhv[0], bhv[1], bhv[2], bhv[3], bHi0 + p*2304 + off);
            LDSM_X4(blv[0], blv[1], blv[2], blv[3], bLo0 + p*2304 + off);
#pragma unroll
            for (int lt = 0; lt < 2; lt++) {
                mma16(acc[lt][2*p],   ah[lt], bhv[0], bhv[1]);
                mma16(acc[lt][2*p],   ah[lt], blv[0], blv[1]);
                mma16(acc[lt][2*p],   al[lt], bhv[0], bhv[1]);
                mma16(acc[lt][2*p+1], ah[lt], bhv[2], bhv[3]);
                mma16(acc[lt][2*p+1], ah[lt], blv[2], blv[3]);
                mma16(acc[lt][2*p+1], al[lt], bhv[2], bhv[3]);
            }
        }
    }
    __syncthreads();   // phase-A operands dead; qpT may overwrite

    // ---- Epilogue 1: exp, tf32 store TRANSPOSED qpT[m][l], ksum from registers ----
    {
        float sqa[2][2];
#pragma unroll
        for (int lt = 0; lt < 2; lt++) {
            const int r1 = lbase + lt*16 + g;
            sqa[lt][0] = smf[SQN1_F + r1];
            sqa[lt][1] = smf[SQN1_F + r1 + 8];
        }
#pragma unroll
        for (int nt = 0; nt < 8; nt++) {
            const int n = n0base + nt*8 + 2*tig;
            float cs0 = 0.f, cs1 = 0.f;
#pragma unroll
            for (int lt = 0; lt < 2; lt++) {
                const int r1 = lbase + lt*16 + g;
                const int r2 = r1 + 8;
                float e00 = __expf(acc[lt][nt][0] - sqa[lt][0] + EPSK);
                float e01 = __expf(acc[lt][nt][1] - sqa[lt][0] + EPSK);
                float e10 = __expf(acc[lt][nt][2] - sqa[lt][1] + EPSK);
                float e11 = __expf(acc[lt][nt][3] - sqa[lt][1] + EPSK);
                cs0 += e00 + e10;
                cs1 += e01 + e11;
                smf[QPT_F + n*QPT_STR + r1]     = tf32r(e00);
                smf[QPT_F + (n+1)*QPT_STR + r1] = tf32r(e01);
                smf[QPT_F + n*QPT_STR + r2]     = tf32r(e10);
                smf[QPT_F + (n+1)*QPT_STR + r2] = tf32r(e11);
            }
            cs0 += __shfl_xor_sync(0xffffffffu, cs0, 4);
            cs0 += __shfl_xor_sync(0xffffffffu, cs0, 8);
            cs0 += __shfl_xor_sync(0xffffffffu, cs0, 16);
            cs1 += __shfl_xor_sync(0xffffffffu, cs1, 4);
            cs1 += __shfl_xor_sync(0xffffffffu, cs1, 8);
            cs1 += __shfl_xor_sync(0xffffffffu, cs1, 16);
            if (lane < 4) {
                smf[PKS_F + w*64 + nt*8 + 2*tig]     = cs0;
                smf[PKS_F + w*64 + nt*8 + 2*tig + 1] = cs1;
            }
        }
    }
    __syncthreads();

    // ---- GEMM2 (tf32): kv_partial[256,64] = qpT[256,128] @ v[128,64]; 16 m-rows/warp ----
    const int m0 = w * 16;
    float acc2[8][4];
#pragma unroll
    for (int nt = 0; nt < 8; nt++)
#pragma unroll
        for (int i = 0; i < 4; i++) acc2[nt][i] = 0.f;

    for (int k8 = 0; k8 < 16; k8++) {
        const int lk = k8 * 8;
        u32 a[4];
        a[0] = f2u(smf[QPT_F + (m0+g)*QPT_STR + lk + tig]);
        a[1] = f2u(smf[QPT_F + (m0+8+g)*QPT_STR + lk + tig]);
        a[2] = f2u(smf[QPT_F + (m0+g)*QPT_STR + lk + tig + 4]);
        a[3] = f2u(smf[QPT_F + (m0+8+g)*QPT_STR + lk + tig + 4]);
#pragma unroll
        for (int nt = 0; nt < 8; nt++) {
            u32 b0 = f2u(smf[V_F + (lk+tig)*VSTR + nt*8 + g]);
            u32 b1 = f2u(smf[V_F + (lk+tig+4)*VSTR + nt*8 + g]);
            mma8(acc2[nt], a, b0, b1);
        }
    }

    // ---- write kv partial + ksum partial ----
    float* pb = g_part + (size_t)(bh*CH2 + tile) * PART_SZ;
    {
        const int r1 = m0 + g, r2 = r1 + 8;
#pragma unroll
        for (int nt = 0; nt < 8; nt++) {
            const int d = nt*8 + 2*tig;
            *(float2*)(pb + r1*D_ + d) = make_float2(acc2[nt][0], acc2[nt][1]);
            *(float2*)(pb + r2*D_ + d) = make_float2(acc2[nt][2], acc2[nt][3]);
        }
    }
    if (t < M_) {
        const int wb = (t >> 6) * 4, nloc = t & 63;
        float s = smf[PKS_F + (wb+0)*64 + nloc]
                + smf[PKS_F + (wb+1)*64 + nloc]
                + smf[PKS_F + (wb+2)*64 + nloc]
                + smf[PKS_F + (wb+3)*64 + nloc];
        pb[M_*D_ + t] = s;
    }
}

// ========== reduce: partials -> ksum fp32, kv tf32-rounded fp32 ==========

__global__ void k_reduce() {
    int idx = blockIdx.x * 256 + threadIdx.x;
    int bh = idx / PART_SZ;
    int r  = idx - bh * PART_SZ;
    const float* p = g_part + (size_t)bh * CH2 * PART_SZ + r;
    float s = 0.f;
#pragma unroll
    for (int c = 0; c < CH2; c++) s += p[(size_t)c * PART_SZ];
    if (r < M_*D_) g_kv[bh*M_*D_ + r] = tf32r(s);
    else           g_ksum[bh*M_ + (r - M_*D_)] = s;
}

// ============================ k2: bf16-GEMM1 + tf32-GEMM2 ============================
#define QHB_W  0
#define QLB_W  4608
#define PHB2_W 9216
#define PLB2_W 18432
#define QP_F   0
#define KV_F   33280
#define SQN_F  51712
#define KSUM_F 51840
#define ZP_F   52096
#define K2_FLOATS 52608
#define K2_SMEM (K2_FLOATS*4)
#define QPSTR 260
#define KVSTR 72

__global__ void __launch_bounds__(NT, 1)
k2_out(const float* __restrict__ qg, float* __restrict__ outg) {
    extern __shared__ float smf[];
    u32* smw = (u32*)smf;
    const int t = threadIdx.x;
    const int lane = t & 31, w = t >> 5;      // 16 warps
    const int g = lane >> 2, tig = lane & 3;
    const int bh = blockIdx.x >> 6, tile = blockIdx.x & 63;
    const int l0 = tile * 128;
    const size_t gbase = (size_t)bh * L_ * D_;

    // ---- copy P bf16 hi/lo ----
    {
        const uint4* sh = (const uint4*)g_Pbh;
        const uint4* sl = (const uint4*)g_Pbl;
#pragma unroll
        for (int i = 0; i < 4; i++) {
            int id = t + i * NT;
            int m = id >> 3, j = id & 7;
            *(uint4*)(smw + PHB2_W + m*BSTR + j*4) = sh[id];
            *(uint4*)(smw + PLB2_W + m*BSTR + j*4) = sl[id];
        }
    }
    // ---- load q tile, scale, bf16 split, sqn via shfl ----
    {
        const int r = t >> 2, c0w = (t & 3) * 8;
        const float4* src = (const float4*)(qg + gbase + (size_t)(l0 + r)*D_ + (t & 3)*16);
        float ss = 0.f;
#pragma unroll
        for (int i = 0; i < 4; i++) {
            float4 x = src[i];
            x.x *= NORMV; x.y *= NORMV; x.z *= NORMV; x.w *= NORMV;
            ss += x.x*x.x + x.y*x.y + x.z*x.z + x.w*x.w;
            u32 h01, l01, h23, l23;
            bsplit2(x.x, x.y, h01, l01);
            bsplit2(x.z, x.w, h23, l23);
            *(uint2*)(smw + QHB_W + r*BSTR + c0w + 2*i) = make_uint2(h01, h23);
            *(uint2*)(smw + QLB_W + r*BSTR + c0w + 2*i) = make_uint2(l01, l23);
        }
        ss += __shfl_xor_sync(0xffffffffu, ss, 1);
        ss += __shfl_xor_sync(0xffffffffu, ss, 2);
        if ((lane & 3) == 0) smf[SQN_F + r] = 0.5f * ss;
    }
    // ---- kv load EARLY (region doesn't alias phase-A operands) ----
    {
        const float4* src = (const float4*)(g_kv + (size_t)bh * M_ * D_);
#pragma unroll
        for (int i = 0; i < 8; i++) {
            int id = t + i * NT;               // 4096 float4
            int m = id >> 4, c4 = id & 15;
            *(float4*)(smf + KV_F + m*KVSTR + c4*4) = src[id];
        }
    }
    if (t < M_) smf[KSUM_F + t] = g_ksum[bh*M_ + t];
    __syncthreads();

    // ---- GEMM1 (bf16 k16, ldmatrix): proj[128,256], warp grid 4x4 ----
    const int lbase = (w & 3) * 32;
    const int n0base = (w >> 2) * 64;
    const int aRow = (lane & 7) + ((lane >> 3) & 1) * 8;
    const int aCol = ((lane >> 4) & 1) * 16;
    const int bRow = (lane & 7) + ((lane >> 4) & 1) * 8;
    const int bCol = ((lane >> 3) & 1) * 16;
    const u32 aHi0 = (u32)__cvta_generic_to_shared(smw + QHB_W + (lbase + aRow)*BSTR) + aCol;
    const u32 aLo0 = (u32)__cvta_generic_to_shared(smw + QLB_W + (lbase + aRow)*BSTR) + aCol;
    const u32 bHi0 = (u32)__cvta_generic_to_shared(smw + PHB2_W + (n0base + bRow)*BSTR) + bCol;
    const u32 bLo0 = (u32)__cvta_generic_to_shared(smw + PLB2_W + (n0base + bRow)*BSTR) + bCol;

    float acc[2][8][4];
#pragma unroll
    for (int lt = 0; lt < 2; lt++)
#pragma unroll
        for (int nt = 0; nt < 8; nt++)
#pragma unroll
            for (int i = 0; i < 4; i++) acc[lt][nt][i] = 0.f;

#pragma unroll
    for (int ks = 0; ks < 4; ks++) {
        const u32 off = ks * 32;
        u32 ah[2][4], al[2][4];
        LDSM_X4(ah[0][0], ah[0][1], ah[0][2], ah[0][3], aHi0 + off);
        LDSM_X4(ah[1][0], ah[1][1], ah[1][2], ah[1][3], aHi0 + 2304 + off);
        LDSM_X4(al[0][0], al[0][1], al[0][2], al[0][3], aLo0 + off);
        LDSM_X4(al[1][0], al[1][1], al[1][2], al[1][3], aLo0 + 2304 + off);
#pragma unroll
        for (int p = 0; p < 4; p++) {
            u32 bhv[4], blv[4];
            LDSM_X4(bhv[0], bhv[1], bhv[2], bhv[3], bHi0 + p*2304 + off);
            LDSM_X4(blv[0], blv[1], blv[2], blv[3], bLo0 + p*2304 + off);
#pragma unroll
            for (int lt = 0; lt < 2; lt++) {
                mma16(acc[lt][2*p],   ah[lt], bhv[0], bhv[1]);
                mma16(acc[lt][2*p],   ah[lt], blv[0], blv[1]);
                mma16(acc[lt][2*p],   al[lt], bhv[0], bhv[1]);
                mma16(acc[lt][2*p+1], ah[lt], bhv[2], bhv[3]);
                mma16(acc[lt][2*p+1], ah[lt], blv[2], blv[3]);
                mma16(acc[lt][2*p+1], al[lt], bhv[2], bhv[3]);
            }
        }
    }
    __syncthreads();

    // ---- Epilogue 1: exp, z-dot, tf32 round, store q' ----
#pragma unroll
    for (int lt = 0; lt < 2; lt++) {
        const int r1 = lbase + lt*16 + g;
        const int r2 = r1 + 8;
        const float sq1 = smf[SQN_F + r1], sq2 = smf[SQN_F + r2];
        float za1 = 0.f, za2 = 0.f;
#pragma unroll
        for (int nt = 0; nt < 8; nt++) {
            const int n = n0base + nt*8 + 2*tig;
            const float ks0 = smf[KSUM_F + n], ks1 = smf[KSUM_F + n + 1];
            float e00 = __expf(acc[lt][nt][0] - sq1 + EPSK);
            float e01 = __expf(acc[lt][nt][1] - sq1 + EPSK);
            float e10 = __expf(acc[lt][nt][2] - sq2 + EPSK);
            float e11 = __expf(acc[lt][nt][3] - sq2 + EPSK);
            za1 += e00*ks0 + e01*ks1;
            za2 += e10*ks0 + e11*ks1;
            *(float2*)(smf + QP_F + r1*QPSTR + n) = make_float2(tf32r(e00), tf32r(e01));
            *(float2*)(smf + QP_F + r2*QPSTR + n) = make_float2(tf32r(e10), tf32r(e11));
        }
        za1 += __shfl_xor_sync(0xffffffffu, za1, 1);
        za1 += __shfl_xor_sync(0xffffffffu, za1, 2);
        za2 += __shfl_xor_sync(0xffffffffu, za2, 1);
        za2 += __shfl_xor_sync(0xffffffffu, za2, 2);
        if (tig == 0) {
            float* zp = smf + ZP_F + (w >> 2) * 128;
            zp[r1] = za1;
            zp[r2] = za2;
        }
    }
    __syncthreads();

    // ---- GEMM2 (tf32): out[128,64] = q'[128,256] @ kv[256,64]; warp grid 8x2 ----
    const int r0 = (w & 7)*16 + g;
    const int colbase = (w >> 3) * 32;
    float acc2[4][4];
#pragma unroll
    for (int nt = 0; nt < 4; nt++)
#pragma unroll
        for (int i = 0; i < 4; i++) acc2[nt][i] = 0.f;

    for (int km = 0; km < 32; km++) {
        const int m0 = km * 8;
        u32 a[4];
        a[0] = f2u(smf[QP_F + r0*QPSTR + m0 + tig]);
        a[1] = f2u(smf[QP_F + (r0+8)*QPSTR + m0 + tig]);
        a[2] = f2u(smf[QP_F + r0*QPSTR + m0 + tig + 4]);
        a[3] = f2u(smf[QP_F + (r0+8)*QPSTR + m0 + tig + 4]);
#pragma unroll
        for (int nt = 0; nt < 4; nt++) {
            u32 b0 = f2u(smf[KV_F + (m0+tig)*KVSTR + colbase + nt*8 + g]);
            u32 b1 = f2u(smf[KV_F + (m0+tig+4)*KVSTR + colbase + nt*8 + g]);
            mma8(acc2[nt], a, b0, b1);
        }
    }

    // ---- Epilogue 2: scale by z (sum of 4 group partials), store ----
    {
        const float* zp = smf + ZP_F;
        const float z1 = 1.0f / (zp[r0] + zp[128 + r0] + zp[256 + r0] + zp[384 + r0] + EPSZ);
        const float z2 = 1.0f / (zp[r0+8] + zp[128 + r0+8] + zp[256 + r0+8] + zp[384 + r0+8] + EPSZ);
        float* o1 = outg + gbase + (size_t)(l0 + r0)*D_ + colbase;
        float* o2 = outg + gbase + (size_t)(l0 + r0 + 8)*D_ + colbase;
#pragma unroll
        for (int nt = 0; nt < 4; nt++) {
            const int d = nt*8 + 2*tig;
            *(float2*)(o1 + d) = make_float2(acc2[nt][0]*z1, acc2[nt][1]*z1);
            *(float2*)(o2 + d) = make_float2(acc2[nt][2]*z2, acc2[nt][3]*z2);
        }
    }
}

extern "C" void kernel_launch(void* const* d_in, const int* in_sizes, int n_in,
                              void* d_out, int out_size) {
    (void)in_sizes; (void)n_in; (void)out_size;
    const float* q = (const float*)d_in[0];
    const float* k = (const float*)d_in[1];
    const float* v = (const float*)d_in[2];
    const float* P = (const float*)d_in[3];
    float* out = (float*)d_out;

    cudaFuncSetAttribute(k1_mma, cudaFuncAttributeMaxDynamicSharedMemorySize, K1_SMEM);
    cudaFuncSetAttribute(k2_out, cudaFuncAttributeMaxDynamicSharedMemorySize, K2_SMEM);

    k_prep_P<<<32, 256>>>(P);
    k1_mma<<<BH_*CH2, NT, K1_SMEM>>>(k, v);
    k_reduce<<<(BH_*PART_SZ)/256, 256>>>();
    k2_out<<<BH_*CH2, NT, K2_SMEM>>>(q, out);
}

// round 14
// speedup vs baseline: 1.0731x; 1.0368x over previous
#include <cuda_runtime.h>
#include <cuda_bf16.h>
#include <cuda_fp16.h>
#include <cstdint>

typedef unsigned int u32;

#define B_ 4
#define H_ 8
#define L_ 8192
#define D_ 64
#define M_ 256
#define BH_ (B_*H_)
#define CH2 64                              // 64 chunks of 128 l-rows
#define NORMV 0.35355339059327373f          // 64^(-1/4)
#define EPSK 1e-6f
#define EPSZ 1e-6f
#define NT 512
#define PSC 0.03125f                        // partial scale 1/32 (exact)
#define PSCI 32.0f

__device__ __align__(16) __half g_parth[BH_*CH2*M_*D_];   // 64 MB fp16 kv partials
__device__ __align__(16) float g_kspart[BH_*CH2*M_];      // 2 MB fp32 ksum partials
__device__ __align__(16) float g_kv[BH_*M_*D_];           // tf32-rounded
__device__ __align__(16) float g_ksum[BH_*M_];            // fp32
__device__ __align__(16) u32 g_Pbh[M_*D_/2];              // bf16-hi pairs
__device__ __align__(16) u32 g_Pbl[M_*D_/2];              // bf16-lo pairs

// ---- tf32 / bf16 / mma helpers ----
__device__ __forceinline__ float tf32r(float x) {
    u32 u; asm("cvt.rna.tf32.f32 %0, %1;" : "=r"(u) : "f"(x));
    return __uint_as_float(u);
}
__device__ __forceinline__ u32 f2u(float x) { return __float_as_uint(x); }
__device__ __forceinline__ u32 bpack(__nv_bfloat16 a, __nv_bfloat16 b) {
    unsigned short ua = *(unsigned short*)&a, ub = *(unsigned short*)&b;
    return (u32)ua | ((u32)ub << 16);
}
__device__ __forceinline__ void bsplit2(float a, float b, u32 &hi, u32 &lo) {
    __nv_bfloat16 ha = __float2bfloat16(a), hb = __float2bfloat16(b);
    float ra = a - __bfloat162float(ha);
    float rb = b - __bfloat162float(hb);
    hi = bpack(ha, hb);
    lo = bpack(__float2bfloat16(ra), __float2bfloat16(rb));
}
__device__ __forceinline__ void mma8(float* c, const u32* a, u32 b0, u32 b1) {
    asm volatile(
        "mma.sync.aligned.m16n8k8.row.col.f32.tf32.tf32.f32 "
        "{%0,%1,%2,%3}, {%4,%5,%6,%7}, {%8,%9}, {%0,%1,%2,%3};"
        : "+f"(c[0]), "+f"(c[1]), "+f"(c[2]), "+f"(c[3])
        : "r"(a[0]), "r"(a[1]), "r"(a[2]), "r"(a[3]), "r"(b0), "r"(b1));
}
__device__ __forceinline__ void mma16(float* c, const u32* a, u32 b0, u32 b1) {
    asm volatile(
        "mma.sync.aligned.m16n8k16.row.col.f32.bf16.bf16.f32 "
        "{%0,%1,%2,%3}, {%4,%5,%6,%7}, {%8,%9}, {%0,%1,%2,%3};"
        : "+f"(c[0]), "+f"(c[1]), "+f"(c[2]), "+f"(c[3])
        : "r"(a[0]), "r"(a[1]), "r"(a[2]), "r"(a[3]), "r"(b0), "r"(b1));
}

// ========== prep: P -> bf16 hi/lo split pairs ==========

__global__ void k_prep_P(const float* __restrict__ Pg) {
    int idx = blockIdx.x * 256 + threadIdx.x;   // 8192 pairs
    float x0 = Pg[2*idx], x1 = Pg[2*idx + 1];
    u32 hi, lo;
    bsplit2(x0, x1, hi, lo);
    g_Pbh[idx] = hi;
    g_Pbl[idx] = lo;
}

// ============================ k1: bf16-GEMM1 + tf32-GEMM2 ============================
#define KHB_W  0
#define KLB_W  4608
#define PHB_W  9216
#define PLB_W  18432
#define QPT_F  0
#define V_F    33792
#define SQN1_F 43008
#define PKS_F  43136
#define K1_FLOATS 44160
#define K1_SMEM (K1_FLOATS*4)
#define BSTR 36
#define QPT_STR 132
#define VSTR 72

__global__ void __launch_bounds__(NT, 1)
k1_mma(const float* __restrict__ kg, const float* __restrict__ vg) {
    extern __shared__ float smf[];
    u32* smw = (u32*)smf;
    const int t = threadIdx.x;
    const int lane = t & 31, w = t >> 5;      // 16 warps
    const int g = lane >> 2, tig = lane & 3;
    const int bh = blockIdx.x >> 6, tile = blockIdx.x & 63;
    const int l0 = tile * 128;
    const size_t gbase = (size_t)bh * L_ * D_;

    // ---- copy P bf16 hi/lo into stride-36 smem ----
    {
        const uint4* sh = (const uint4*)g_Pbh;   // 2048 uint4
        const uint4* sl = (const uint4*)g_Pbl;
#pragma unroll
        for (int i = 0; i < 4; i++) {
            int id = t + i * NT;
            int m = id >> 3, j = id & 7;
            *(uint4*)(smw + PHB_W + m*BSTR + j*4) = sh[id];
            *(uint4*)(smw + PLB_W + m*BSTR + j*4) = sl[id];
        }
    }
    // ---- load k tile, scale, bf16 split, sqn via shfl ----
    {
        const int r = t >> 2, c0w = (t & 3) * 8;
        const float4* src = (const float4*)(kg + gbase + (size_t)(l0 + r)*D_ + (t & 3)*16);
        float ss = 0.f;
#pragma unroll
        for (int i = 0; i < 4; i++) {
            float4 x = src[i];
            x.x *= NORMV; x.y *= NORMV; x.z *= NORMV; x.w *= NORMV;
            ss += x.x*x.x + x.y*x.y + x.z*x.z + x.w*x.w;
            u32 h01, l01, h23, l23;
            bsplit2(x.x, x.y, h01, l01);
            bsplit2(x.z, x.w, h23, l23);
            *(uint2*)(smw + KHB_W + r*BSTR + c0w + 2*i) = make_uint2(h01, h23);
            *(uint2*)(smw + KLB_W + r*BSTR + c0w + 2*i) = make_uint2(l01, l23);
        }
        ss += __shfl_xor_sync(0xffffffffu, ss, 1);
        ss += __shfl_xor_sync(0xffffffffu, ss, 2);
        if ((lane & 3) == 0) smf[SQN1_F + r] = 0.5f * ss;
    }
    // ---- v tile (tf32-rounded) EARLY: region doesn't alias phase-A operands ----
    {
        const float4* src = (const float4*)(vg + gbase + (size_t)l0*D_);
#pragma unroll
        for (int i = 0; i < 4; i++) {
            int id = t + i * NT;               // 2048 float4
            int l = id >> 4, c4 = id & 15;
            float4 x = src[id];
            x.x = tf32r(x.x); x.y = tf32r(x.y); x.z = tf32r(x.z); x.w = tf32r(x.w);
            *(float4*)(smf + V_F + l*VSTR + c4*4) = x;
        }
    }
    __syncthreads();

    // ---- GEMM1 (bf16 k16): proj[128,256], warp grid 4x4, 32x64/warp, 3 products ----
    const int lbase = (w & 3) * 32;
    const int n0base = (w >> 2) * 64;
    float acc[2][8][4];
#pragma unroll
    for (int lt = 0; lt < 2; lt++)
#pragma unroll
        for (int nt = 0; nt < 8; nt++)
#pragma unroll
            for (int i = 0; i < 4; i++) acc[lt][nt][i] = 0.f;

#pragma unroll
    for (int ks = 0; ks < 4; ks++) {
        const int k0w = ks * 8;
        u32 ah[2][4], al[2][4];
#pragma unroll
        for (int lt = 0; lt < 2; lt++) {
            const int base = (lbase + lt*16 + g)*BSTR + k0w + tig;
            ah[lt][0] = smw[KHB_W + base];
            ah[lt][1] = smw[KHB_W + base + 8*BSTR];
            ah[lt][2] = smw[KHB_W + base + 4];
            ah[lt][3] = smw[KHB_W + base + 8*BSTR + 4];
            al[lt][0] = smw[KLB_W + base];
            al[lt][1] = smw[KLB_W + base + 8*BSTR];
            al[lt][2] = smw[KLB_W + base + 4];
            al[lt][3] = smw[KLB_W + base + 8*BSTR + 4];
        }
#pragma unroll
        for (int nt = 0; nt < 8; nt++) {
            const int bb = (n0base + nt*8 + g)*BSTR + k0w + tig;
            u32 bh0 = smw[PHB_W + bb];
            u32 bh1 = smw[PHB_W + bb + 4];
            u32 bl0 = smw[PLB_W + bb];
            u32 bl1 = smw[PLB_W + bb + 4];
#pragma unroll
            for (int lt = 0; lt < 2; lt++) {
                mma16(acc[lt][nt], ah[lt], bh0, bh1);
                mma16(acc[lt][nt], ah[lt], bl0, bl1);
                mma16(acc[lt][nt], al[lt], bh0, bh1);
            }
        }
    }
    __syncthreads();   // phase-A operands dead; qpT may overwrite

    // ---- Epilogue 1: exp, tf32 store TRANSPOSED qpT[m][l], ksum from registers ----
    {
        float sqa[2][2];
#pragma unroll
        for (int lt = 0; lt < 2; lt++) {
            const int r1 = lbase + lt*16 + g;
            sqa[lt][0] = smf[SQN1_F + r1];
            sqa[lt][1] = smf[SQN1_F + r1 + 8];
        }
#pragma unroll
        for (int nt = 0; nt < 8; nt++) {
            const int n = n0base + nt*8 + 2*tig;
            float cs0 = 0.f, cs1 = 0.f;
#pragma unroll
            for (int lt = 0; lt < 2; lt++) {
                const int r1 = lbase + lt*16 + g;
                const int r2 = r1 + 8;
                float e00 = __expf(acc[lt][nt][0] - sqa[lt][0] + EPSK);
                float e01 = __expf(acc[lt][nt][1] - sqa[lt][0] + EPSK);
                float e10 = __expf(acc[lt][nt][2] - sqa[lt][1] + EPSK);
                float e11 = __expf(acc[lt][nt][3] - sqa[lt][1] + EPSK);
                cs0 += e00 + e10;
                cs1 += e01 + e11;
                smf[QPT_F + n*QPT_STR + r1]     = tf32r(e00);
                smf[QPT_F + (n+1)*QPT_STR + r1] = tf32r(e01);
                smf[QPT_F + n*QPT_STR + r2]     = tf32r(e10);
                smf[QPT_F + (n+1)*QPT_STR + r2] = tf32r(e11);
            }
            cs0 += __shfl_xor_sync(0xffffffffu, cs0, 4);
            cs0 += __shfl_xor_sync(0xffffffffu, cs0, 8);
            cs0 += __shfl_xor_sync(0xffffffffu, cs0, 16);
            cs1 += __shfl_xor_sync(0xffffffffu, cs1, 4);
            cs1 += __shfl_xor_sync(0xffffffffu, cs1, 8);
            cs1 += __shfl_xor_sync(0xffffffffu, cs1, 16);
            if (lane < 4) {
                smf[PKS_F + w*64 + nt*8 + 2*tig]     = cs0;
                smf[PKS_F + w*64 + nt*8 + 2*tig + 1] = cs1;
            }
        }
    }
    __syncthreads();

    // ---- GEMM2 (tf32): kv_partial[256,64] = qpT[256,128] @ v[128,64]; 16 m-rows/warp ----
    const int m0 = w * 16;
    float acc2[8][4];
#pragma unroll
    for (int nt = 0; nt < 8; nt++)
#pragma unroll
        for (int i = 0; i < 4; i++) acc2[nt][i] = 0.f;

    for (int k8 = 0; k8 < 16; k8++) {
        const int lk = k8 * 8;
        u32 a[4];
        a[0] = f2u(smf[QPT_F + (m0+g)*QPT_STR + lk + tig]);
        a[1] = f2u(smf[QPT_F + (m0+8+g)*QPT_STR + lk + tig]);
        a[2] = f2u(smf[QPT_F + (m0+g)*QPT_STR + lk + tig + 4]);
        a[3] = f2u(smf[QPT_F + (m0+8+g)*QPT_STR + lk + tig + 4]);
#pragma unroll
        for (int nt = 0; nt < 8; nt++) {
            u32 b0 = f2u(smf[V_F + (lk+tig)*VSTR + nt*8 + g]);
            u32 b1 = f2u(smf[V_F + (lk+tig+4)*VSTR + nt*8 + g]);
            mma8(acc2[nt], a, b0, b1);
        }
    }

    // ---- write kv partial (scaled fp16) + ksum partial (fp32) ----
    __half* pb = g_parth + (size_t)(bh*CH2 + tile) * (M_*D_);
    {
        const int r1 = m0 + g, r2 = r1 + 8;
#pragma unroll
        for (int nt = 0; nt < 8; nt++) {
            const int d = nt*8 + 2*tig;
            *(__half2*)(pb + r1*D_ + d) =
                __floats2half2_rn(acc2[nt][0]*PSC, acc2[nt][1]*PSC);
            *(__half2*)(pb + r2*D_ + d) =
                __floats2half2_rn(acc2[nt][2]*PSC, acc2[nt][3]*PSC);
        }
    }
    if (t < M_) {
        const int wb = (t >> 6) * 4, nloc = t & 63;
        float s = smf[PKS_F + (wb+0)*64 + nloc]
                + smf[PKS_F + (wb+1)*64 + nloc]
                + smf[PKS_F + (wb+2)*64 + nloc]
                + smf[PKS_F + (wb+3)*64 + nloc];
        g_kspart[(size_t)(bh*CH2 + tile)*M_ + t] = s;
    }
}

// ========== reduce: fp16 partials -> kv (tf32); fp32 ksum partials -> ksum ==========

__global__ void k_reduce() {
    const int bid = blockIdx.x, t = threadIdx.x;
    if (bid < 1024) {
        // kv: half2 elements, 2 outputs per thread
        int gid = bid * 256 + t;            // [0, 262144)
        int bh = gid >> 13;
        int rr = gid & 8191;
        const __half2* p = (const __half2*)g_parth + (size_t)bh * CH2 * 8192 + rr;
        float sx = 0.f, sy = 0.f;
#pragma unroll
        for (int c = 0; c < CH2; c++) {
            float2 f = __half22float2(p[(size_t)c * 8192]);
            sx += f.x; sy += f.y;
        }
        g_kv[bh*M_*D_ + 2*rr]     = tf32r(sx * PSCI);
        g_kv[bh*M_*D_ + 2*rr + 1] = tf32r(sy * PSCI);
    } else {
        int j = (bid - 1024) * 256 + t;     // [0, 8192)
        int bh = j >> 8, n = j & 255;
        const float* p = g_kspart + (size_t)bh * CH2 * M_ + n;
        float s = 0.f;
#pragma unroll
        for (int c = 0; c < CH2; c++) s += p[(size_t)c * M_];
        g_ksum[bh*M_ + n] = s;
    }
}

// ============================ k2: bf16-GEMM1 + tf32-GEMM2 ============================
#define QHB_W  0
#define QLB_W  4608
#define PHB2_W 9216
#define PLB2_W 18432
#define QP_F   0
#define KV_F   33280
#define SQN_F  51712
#define KSUM_F 51840
#define ZP_F   52096
#define K2_FLOATS 52608
#define K2_SMEM (K2_FLOATS*4)
#define QPSTR 260
#define KVSTR 72

__global__ void __launch_bounds__(NT, 1)
k2_out(const float* __restrict__ qg, float* __restrict__ outg) {
    extern __shared__ float smf[];
    u32* smw = (u32*)smf;
    const int t = threadIdx.x;
    const int lane = t & 31, w = t >> 5;      // 16 warps
    const int g = lane >> 2, tig = lane & 3;
    const int bh = blockIdx.x >> 6, tile = blockIdx.x & 63;
    const int l0 = tile * 128;
    const size_t gbase = (size_t)bh * L_ * D_;

    // ---- copy P bf16 hi/lo ----
    {
        const uint4* sh = (const uint4*)g_Pbh;
        const uint4* sl = (const uint4*)g_Pbl;
#pragma unroll
        for (int i = 0; i < 4; i++) {
            int id = t + i * NT;
            int m = id >> 3, j = id & 7;
            *(uint4*)(smw + PHB2_W + m*BSTR + j*4) = sh[id];
            *(uint4*)(smw + PLB2_W + m*BSTR + j*4) = sl[id];
        }
    }
    // ---- load q tile, scale, bf16 split, sqn via shfl ----
    {
        const int r = t >> 2, c0w = (t & 3) * 8;
        const float4* src = (const float4*)(qg + gbase + (size_t)(l0 + r)*D_ + (t & 3)*16);
        float ss = 0.f;
#pragma unroll
        for (int i = 0; i < 4; i++) {
            float4 x = src[i];
            x.x *= NORMV; x.y *= NORMV; x.z *= NORMV; x.w *= NORMV;
            ss += x.x*x.x + x.y*x.y + x.z*x.z + x.w*x.w;
            u32 h01, l01, h23, l23;
            bsplit2(x.x, x.y, h01, l01);
            bsplit2(x.z, x.w, h23, l23);
            *(uint2*)(smw + QHB_W + r*BSTR + c0w + 2*i) = make_uint2(h01, h23);
            *(uint2*)(smw + QLB_W + r*BSTR + c0w + 2*i) = make_uint2(l01, l23);
        }
        ss += __shfl_xor_sync(0xffffffffu, ss, 1);
        ss += __shfl_xor_sync(0xffffffffu, ss, 2);
        if ((lane & 3) == 0) smf[SQN_F + r] = 0.5f * ss;
    }
    // ---- kv load EARLY (region doesn't alias phase-A operands) ----
    {
        const float4* src = (const float4*)(g_kv + (size_t)bh * M_ * D_);
#pragma unroll
        for (int i = 0; i < 8; i++) {
            int id = t + i * NT;               // 4096 float4
            int m = id >> 4, c4 = id & 15;
            *(float4*)(smf + KV_F + m*KVSTR + c4*4) = src[id];
        }
    }
    if (t < M_) smf[KSUM_F + t] = g_ksum[bh*M_ + t];
    __syncthreads();

    // ---- GEMM1 (bf16 k16): proj[128,256], warp grid 4x4, 3 products ----
    const int lbase = (w & 3) * 32;
    const int n0base = (w >> 2) * 64;
    float acc[2][8][4];
#pragma unroll
    for (int lt = 0; lt < 2; lt++)
#pragma unroll
        for (int nt = 0; nt < 8; nt++)
#pragma unroll
            for (int i = 0; i < 4; i++) acc[lt][nt][i] = 0.f;

#pragma unroll
    for (int ks = 0; ks < 4; ks++) {
        const int k0w = ks * 8;
        u32 ah[2][4], al[2][4];
#pragma unroll
        for (int lt = 0; lt < 2; lt++) {
            const int base = (lbase + lt*16 + g)*BSTR + k0w + tig;
            ah[lt][0] = smw[QHB_W + base];
            ah[lt][1] = smw[QHB_W + base + 8*BSTR];
            ah[lt][2] = smw[QHB_W + base + 4];
            ah[lt][3] = smw[QHB_W + base + 8*BSTR + 4];
            al[lt][0] = smw[QLB_W + base];
            al[lt][1] = smw[QLB_W + base + 8*BSTR];
            al[lt][2] = smw[QLB_W + base + 4];
            al[lt][3] = smw[QLB_W + base + 8*BSTR + 4];
        }
#pragma unroll
        for (int nt = 0; nt < 8; nt++) {
            const int bb = (n0base + nt*8 + g)*BSTR + k0w + tig;
            u32 bh0 = smw[PHB2_W + bb];
            u32 bh1 = smw[PHB2_W + bb + 4];
            u32 bl0 = smw[PLB2_W + bb];
            u32 bl1 = smw[PLB2_W + bb + 4];
#pragma unroll
            for (int lt = 0; lt < 2; lt++) {
                mma16(acc[lt][nt], ah[lt], bh0, bh1);
                mma16(acc[lt][nt], ah[lt], bl0, bl1);
                mma16(acc[lt][nt], al[lt], bh0, bh1);
            }
        }
    }
    __syncthreads();

    // ---- Epilogue 1: exp, z-dot, tf32 round, store q' ----
#pragma unroll
    for (int lt = 0; lt < 2; lt++) {
        const int r1 = lbase + lt*16 + g;
        const int r2 = r1 + 8;
        const float sq1 = smf[SQN_F + r1], sq2 = smf[SQN_F + r2];
        float za1 = 0.f, za2 = 0.f;
#pragma unroll
        for (int nt = 0; nt < 8; nt++) {
            const int n = n0base + nt*8 + 2*tig;
            const float ks0 = smf[KSUM_F + n], ks1 = smf[KSUM_F + n + 1];
            float e00 = __expf(acc[lt][nt][0] - sq1 + EPSK);
            float e01 = __expf(acc[lt][nt][1] - sq1 + EPSK);
            float e10 = __expf(acc[lt][nt][2] - sq2 + EPSK);
            float e11 = __expf(acc[lt][nt][3] - sq2 + EPSK);
            za1 += e00*ks0 + e01*ks1;
            za2 += e10*ks0 + e11*ks1;
            *(float2*)(smf + QP_F + r1*QPSTR + n) = make_float2(tf32r(e00), tf32r(e01));
            *(float2*)(smf + QP_F + r2*QPSTR + n) = make_float2(tf32r(e10), tf32r(e11));
        }
        za1 += __shfl_xor_sync(0xffffffffu, za1, 1);
        za1 += __shfl_xor_sync(0xffffffffu, za1, 2);
        za2 += __shfl_xor_sync(0xffffffffu, za2, 1);
        za2 += __shfl_xor_sync(0xffffffffu, za2, 2);
        if (tig == 0) {
            float* zp = smf + ZP_F + (w >> 2) * 128;
            zp[r1] = za1;
            zp[r2] = za2;
        }
    }
    __syncthreads();

    // ---- GEMM2 (tf32): out[128,64] = q'[128,256] @ kv[256,64]; warp grid 8x2 ----
    const int r0 = (w & 7)*16 + g;
    const int colbase = (w >> 3) * 32;
    float acc2[4][4];
#pragma unroll
    for (int nt = 0; nt < 4; nt++)
#pragma unroll
        for (int i = 0; i < 4; i++) acc2[nt][i] = 0.f;

    for (int km = 0; km < 32; km++) {
        const int m0 = km * 8;
        u32 a[4];
        a[0] = f2u(smf[QP_F + r0*QPSTR + m0 + tig]);
        a[1] = f2u(smf[QP_F + (r0+8)*QPSTR + m0 + tig]);
        a[2] = f2u(smf[QP_F + r0*QPSTR + m0 + tig + 4]);
        a[3] = f2u(smf[QP_F + (r0+8)*QPSTR + m0 + tig + 4]);
#pragma unroll
        for (int nt = 0; nt < 4; nt++) {
            u32 b0 = f2u(smf[KV_F + (m0+tig)*KVSTR + colbase + nt*8 + g]);
            u32 b1 = f2u(smf[KV_F + (m0+tig+4)*KVSTR + colbase + nt*8 + g]);
            mma8(acc2[nt], a, b0, b1);
        }
    }

    // ---- Epilogue 2: scale by z (sum of 4 group partials), store ----
    {
        const float* zp = smf + ZP_F;
        const float z1 = 1.0f / (zp[r0] + zp[128 + r0] + zp[256 + r0] + zp[384 + r0] + EPSZ);
        const float z2 = 1.0f / (zp[r0+8] + zp[128 + r0+8] + zp[256 + r0+8] + zp[384 + r0+8] + EPSZ);
        float* o1 = outg + gbase + (size_t)(l0 + r0)*D_ + colbase;
        float* o2 = outg + gbase + (size_t)(l0 + r0 + 8)*D_ + colbase;
#pragma unroll
        for (int nt = 0; nt < 4; nt++) {
            const int d = nt*8 + 2*tig;
            *(float2*)(o1 + d) = make_float2(acc2[nt][0]*z1, acc2[nt][1]*z1);
            *(float2*)(o2 + d) = make_float2(acc2[nt][2]*z2, acc2[nt][3]*z2);
        }
    }
}

extern "C" void kernel_launch(void* const* d_in, const int* in_sizes, int n_in,
                              void* d_out, int out_size) {
    (void)in_sizes; (void)n_in; (void)out_size;
    const float* q = (const float*)d_in[0];
    const float* k = (const float*)d_in[1];
    const float* v = (const float*)d_in[2];
    const float* P = (const float*)d_in[3];
    float* out = (float*)d_out;

    cudaFuncSetAttribute(k1_mma, cudaFuncAttributeMaxDynamicSharedMemorySize, K1_SMEM);
    cudaFuncSetAttribute(k2_out, cudaFuncAttributeMaxDynamicSharedMemorySize, K2_SMEM);

    k_prep_P<<<32, 256>>>(P);
    k1_mma<<<BH_*CH2, NT, K1_SMEM>>>(k, v);
    k_reduce<<<1056, 256>>>();
    k2_out<<<BH_*CH2, NT, K2_SMEM>>>(q, out);
}

// round 15
// speedup vs baseline: 1.0851x; 1.0112x over previous
#include <cuda_runtime.h>
#include <cuda_bf16.h>
#include <cuda_fp16.h>
#include <cstdint>

typedef unsigned int u32;

#define B_ 4
#define H_ 8
#define L_ 8192
#define D_ 64
#define M_ 256
#define BH_ (B_*H_)
#define CH2 64                              // 64 chunks of 128 l-rows
#define NORMV 0.35355339059327373f          // 64^(-1/4)
#define EPSK 1e-6f
#define EPSZ 1e-6f
#define NT 512
#define PSC 0.03125f                        // partial scale 1/32 (exact)
#define PSCI 32.0f

__device__ __align__(16) __half g_parth[BH_*CH2*M_*D_];   // 64 MB fp16 kv partials
__device__ __align__(16) float g_kspart[BH_*CH2*M_];      // 2 MB fp32 ksum partials
__device__ __align__(16) float g_kv[BH_*M_*D_];           // tf32-rounded
__device__ __align__(16) float g_ksum[BH_*M_];            // fp32
__device__ __align__(16) u32 g_Pbh[M_*D_/2];              // bf16-hi pairs
__device__ __align__(16) u32 g_Pbl[M_*D_/2];              // bf16-lo pairs

// ---- tf32 / bf16 / mma helpers ----
__device__ __forceinline__ float tf32r(float x) {
    u32 u; asm("cvt.rna.tf32.f32 %0, %1;" : "=r"(u) : "f"(x));
    return __uint_as_float(u);
}
__device__ __forceinline__ u32 f2u(float x) { return __float_as_uint(x); }
__device__ __forceinline__ u32 bpack(__nv_bfloat16 a, __nv_bfloat16 b) {
    unsigned short ua = *(unsigned short*)&a, ub = *(unsigned short*)&b;
    return (u32)ua | ((u32)ub << 16);
}
__device__ __forceinline__ void bsplit2(float a, float b, u32 &hi, u32 &lo) {
    __nv_bfloat16 ha = __float2bfloat16(a), hb = __float2bfloat16(b);
    float ra = a - __bfloat162float(ha);
    float rb = b - __bfloat162float(hb);
    hi = bpack(ha, hb);
    lo = bpack(__float2bfloat16(ra), __float2bfloat16(rb));
}
__device__ __forceinline__ void mma8(float* c, const u32* a, u32 b0, u32 b1) {
    asm volatile(
        "mma.sync.aligned.m16n8k8.row.col.f32.tf32.tf32.f32 "
        "{%0,%1,%2,%3}, {%4,%5,%6,%7}, {%8,%9}, {%0,%1,%2,%3};"
        : "+f"(c[0]), "+f"(c[1]), "+f"(c[2]), "+f"(c[3])
        : "r"(a[0]), "r"(a[1]), "r"(a[2]), "r"(a[3]), "r"(b0), "r"(b1));
}
__device__ __forceinline__ void mma16(float* c, const u32* a, u32 b0, u32 b1) {
    asm volatile(
        "mma.sync.aligned.m16n8k16.row.col.f32.bf16.bf16.f32 "
        "{%0,%1,%2,%3}, {%4,%5,%6,%7}, {%8,%9}, {%0,%1,%2,%3};"
        : "+f"(c[0]), "+f"(c[1]), "+f"(c[2]), "+f"(c[3])
        : "r"(a[0]), "r"(a[1]), "r"(a[2]), "r"(a[3]), "r"(b0), "r"(b1));
}

// ========== prep: P -> bf16 hi/lo split pairs ==========

__global__ void k_prep_P(const float* __restrict__ Pg) {
    int idx = blockIdx.x * 256 + threadIdx.x;   // 8192 pairs
    float x0 = Pg[2*idx], x1 = Pg[2*idx + 1];
    u32 hi, lo;
    bsplit2(x0, x1, hi, lo);
    g_Pbh[idx] = hi;
    g_Pbl[idx] = lo;
}

// ============================ k1: bf16-GEMM1 + tf32-GEMM2 (R14, proven) ============================
#define KHB_W  0
#define KLB_W  4608
#define PHB_W  9216
#define PLB_W  18432
#define QPT_F  0
#define V_F    33792
#define SQN1_F 43008
#define PKS_F  43136
#define K1_FLOATS 44160
#define K1_SMEM (K1_FLOATS*4)
#define BSTR 36
#define QPT_STR 132
#define VSTR 72

__global__ void __launch_bounds__(NT, 1)
k1_mma(const float* __restrict__ kg, const float* __restrict__ vg) {
    extern __shared__ float smf[];
    u32* smw = (u32*)smf;
    const int t = threadIdx.x;
    const int lane = t & 31, w = t >> 5;      // 16 warps
    const int g = lane >> 2, tig = lane & 3;
    const int bh = blockIdx.x >> 6, tile = blockIdx.x & 63;
    const int l0 = tile * 128;
    const size_t gbase = (size_t)bh * L_ * D_;

    {
        const uint4* sh = (const uint4*)g_Pbh;   // 2048 uint4
        const uint4* sl = (const uint4*)g_Pbl;
#pragma unroll
        for (int i = 0; i < 4; i++) {
            int id = t + i * NT;
            int m = id >> 3, j = id & 7;
            *(uint4*)(smw + PHB_W + m*BSTR + j*4) = sh[id];
            *(uint4*)(smw + PLB_W + m*BSTR + j*4) = sl[id];
        }
    }
    {
        const int r = t >> 2, c0w = (t & 3) * 8;
        const float4* src = (const float4*)(kg + gbase + (size_t)(l0 + r)*D_ + (t & 3)*16);
        float ss = 0.f;
#pragma unroll
        for (int i = 0; i < 4; i++) {
            float4 x = src[i];
            x.x *= NORMV; x.y *= NORMV; x.z *= NORMV; x.w *= NORMV;
            ss += x.x*x.x + x.y*x.y + x.z*x.z + x.w*x.w;
            u32 h01, l01, h23, l23;
            bsplit2(x.x, x.y, h01, l01);
            bsplit2(x.z, x.w, h23, l23);
            *(uint2*)(smw + KHB_W + r*BSTR + c0w + 2*i) = make_uint2(h01, h23);
            *(uint2*)(smw + KLB_W + r*BSTR + c0w + 2*i) = make_uint2(l01, l23);
        }
        ss += __shfl_xor_sync(0xffffffffu, ss, 1);
        ss += __shfl_xor_sync(0xffffffffu, ss, 2);
        if ((lane & 3) == 0) smf[SQN1_F + r] = 0.5f * ss;
    }
    {
        const float4* src = (const float4*)(vg + gbase + (size_t)l0*D_);
#pragma unroll
        for (int i = 0; i < 4; i++) {
            int id = t + i * NT;               // 2048 float4
            int l = id >> 4, c4 = id & 15;
            float4 x = src[id];
            x.x = tf32r(x.x); x.y = tf32r(x.y); x.z = tf32r(x.z); x.w = tf32r(x.w);
            *(float4*)(smf + V_F + l*VSTR + c4*4) = x;
        }
    }
    __syncthreads();

    const int lbase = (w & 3) * 32;
    const int n0base = (w >> 2) * 64;
    float acc[2][8][4];
#pragma unroll
    for (int lt = 0; lt < 2; lt++)
#pragma unroll
        for (int nt = 0; nt < 8; nt++)
#pragma unroll
            for (int i = 0; i < 4; i++) acc[lt][nt][i] = 0.f;

#pragma unroll
    for (int ks = 0; ks < 4; ks++) {
        const int k0w = ks * 8;
        u32 ah[2][4], al[2][4];
#pragma unroll
        for (int lt = 0; lt < 2; lt++) {
            const int base = (lbase + lt*16 + g)*BSTR + k0w + tig;
            ah[lt][0] = smw[KHB_W + base];
            ah[lt][1] = smw[KHB_W + base + 8*BSTR];
            ah[lt][2] = smw[KHB_W + base + 4];
            ah[lt][3] = smw[KHB_W + base + 8*BSTR + 4];
            al[lt][0] = smw[KLB_W + base];
            al[lt][1] = smw[KLB_W + base + 8*BSTR];
            al[lt][2] = smw[KLB_W + base + 4];
            al[lt][3] = smw[KLB_W + base + 8*BSTR + 4];
        }
#pragma unroll
        for (int nt = 0; nt < 8; nt++) {
            const int bb = (n0base + nt*8 + g)*BSTR + k0w + tig;
            u32 bh0 = smw[PHB_W + bb];
            u32 bh1 = smw[PHB_W + bb + 4];
            u32 bl0 = smw[PLB_W + bb];
            u32 bl1 = smw[PLB_W + bb + 4];
#pragma unroll
            for (int lt = 0; lt < 2; lt++) {
                mma16(acc[lt][nt], ah[lt], bh0, bh1);
                mma16(acc[lt][nt], ah[lt], bl0, bl1);
                mma16(acc[lt][nt], al[lt], bh0, bh1);
            }
        }
    }
    __syncthreads();

    {
        float sqa[2][2];
#pragma unroll
        for (int lt = 0; lt < 2; lt++) {
            const int r1 = lbase + lt*16 + g;
            sqa[lt][0] = smf[SQN1_F + r1];
            sqa[lt][1] = smf[SQN1_F + r1 + 8];
        }
#pragma unroll
        for (int nt = 0; nt < 8; nt++) {
            const int n = n0base + nt*8 + 2*tig;
            float cs0 = 0.f, cs1 = 0.f;
#pragma unroll
            for (int lt = 0; lt < 2; lt++) {
                const int r1 = lbase + lt*16 + g;
                const int r2 = r1 + 8;
                float e00 = __expf(acc[lt][nt][0] - sqa[lt][0] + EPSK);
                float e01 = __expf(acc[lt][nt][1] - sqa[lt][0] + EPSK);
                float e10 = __expf(acc[lt][nt][2] - sqa[lt][1] + EPSK);
                float e11 = __expf(acc[lt][nt][3] - sqa[lt][1] + EPSK);
                cs0 += e00 + e10;
                cs1 += e01 + e11;
                smf[QPT_F + n*QPT_STR + r1]     = tf32r(e00);
                smf[QPT_F + (n+1)*QPT_STR + r1] = tf32r(e01);
                smf[QPT_F + n*QPT_STR + r2]     = tf32r(e10);
                smf[QPT_F + (n+1)*QPT_STR + r2] = tf32r(e11);
            }
            cs0 += __shfl_xor_sync(0xffffffffu, cs0, 4);
            cs0 += __shfl_xor_sync(0xffffffffu, cs0, 8);
            cs0 += __shfl_xor_sync(0xffffffffu, cs0, 16);
            cs1 += __shfl_xor_sync(0xffffffffu, cs1, 4);
            cs1 += __shfl_xor_sync(0xffffffffu, cs1, 8);
            cs1 += __shfl_xor_sync(0xffffffffu, cs1, 16);
            if (lane < 4) {
                smf[PKS_F + w*64 + nt*8 + 2*tig]     = cs0;
                smf[PKS_F + w*64 + nt*8 + 2*tig + 1] = cs1;
            }
        }
    }
    __syncthreads();

    const int m0 = w * 16;
    float acc2[8][4];
#pragma unroll
    for (int nt = 0; nt < 8; nt++)
#pragma unroll
        for (int i = 0; i < 4; i++) acc2[nt][i] = 0.f;

    for (int k8 = 0; k8 < 16; k8++) {
        const int lk = k8 * 8;
        u32 a[4];
        a[0] = f2u(smf[QPT_F + (m0+g)*QPT_STR + lk + tig]);
        a[1] = f2u(smf[QPT_F + (m0+8+g)*QPT_STR + lk + tig]);
        a[2] = f2u(smf[QPT_F + (m0+g)*QPT_STR + lk + tig + 4]);
        a[3] = f2u(smf[QPT_F + (m0+8+g)*QPT_STR + lk + tig + 4]);
#pragma unroll
        for (int nt = 0; nt < 8; nt++) {
            u32 b0 = f2u(smf[V_F + (lk+tig)*VSTR + nt*8 + g]);
            u32 b1 = f2u(smf[V_F + (lk+tig+4)*VSTR + nt*8 + g]);
            mma8(acc2[nt], a, b0, b1);
        }
    }

    __half* pb = g_parth + (size_t)(bh*CH2 + tile) * (M_*D_);
    {
        const int r1 = m0 + g, r2 = r1 + 8;
#pragma unroll
        for (int nt = 0; nt < 8; nt++) {
            const int d = nt*8 + 2*tig;
            *(__half2*)(pb + r1*D_ + d) =
                __floats2half2_rn(acc2[nt][0]*PSC, acc2[nt][1]*PSC);
            *(__half2*)(pb + r2*D_ + d) =
                __floats2half2_rn(acc2[nt][2]*PSC, acc2[nt][3]*PSC);
        }
    }
    if (t < M_) {
        const int wb = (t >> 6) * 4, nloc = t & 63;
        float s = smf[PKS_F + (wb+0)*64 + nloc]
                + smf[PKS_F + (wb+1)*64 + nloc]
                + smf[PKS_F + (wb+2)*64 + nloc]
                + smf[PKS_F + (wb+3)*64 + nloc];
        g_kspart[(size_t)(bh*CH2 + tile)*M_ + t] = s;
    }
}

// ========== reduce: fp16 partials -> kv (tf32); fp32 ksum partials -> ksum ==========

__global__ void k_reduce() {
    const int bid = blockIdx.x, t = threadIdx.x;
    if (bid < 1024) {
        int gid = bid * 256 + t;            // [0, 262144)
        int bh = gid >> 13;
        int rr = gid & 8191;
        const __half2* p = (const __half2*)g_parth + (size_t)bh * CH2 * 8192 + rr;
        float sx = 0.f, sy = 0.f;
#pragma unroll
        for (int c = 0; c < CH2; c++) {
            float2 f = __half22float2(p[(size_t)c * 8192]);
            sx += f.x; sy += f.y;
        }
        g_kv[bh*M_*D_ + 2*rr]     = tf32r(sx * PSCI);
        g_kv[bh*M_*D_ + 2*rr + 1] = tf32r(sy * PSCI);
    } else {
        int j = (bid - 1024) * 256 + t;     // [0, 8192)
        int bh = j >> 8, n = j & 255;
        const float* p = g_kspart + (size_t)bh * CH2 * M_ + n;
        float s = 0.f;
#pragma unroll
        for (int c = 0; c < CH2; c++) s += p[(size_t)c * M_];
        g_ksum[bh*M_ + n] = s;
    }
}

// ============= k2: m-quartered, 2 CTAs/SM (109.5 KB smem, <=64 regs) =============
// word/float offsets:
//  QHB@0 (4608) QLB@4608 (4608) | PQH@9216 (2304) PQL@11520 (2304)
//  QPq@13824 (128*68=8704) | KVq@22528 (64*72=4608)
//  SQN@27136(128) KSUM@27264(256) ZP@27520(512) -> 28032 floats = 112128 B
#define QHB2_W 0
#define QLB2_W 4608
#define PQH_W  9216
#define PQL_W  11520
#define QPQ_F  13824
#define KVQ_F  22528
#define SQN2_F 27136
#define KSM2_F 27264
#define ZP2_F  27520
#define K2_FLOATS 28032
#define K2_SMEM (K2_FLOATS*4)
#define QPQ_STR 68
#define KVQ_STR 72

__global__ void __launch_bounds__(NT, 2)
k2_out(const float* __restrict__ qg, float* __restrict__ outg) {
    extern __shared__ float smf[];
    u32* smw = (u32*)smf;
    const int t = threadIdx.x;
    const int lane = t & 31, w = t >> 5;      // 16 warps
    const int g = lane >> 2, tig = lane & 3;
    const int bh = blockIdx.x >> 6, tile = blockIdx.x & 63;
    const int l0 = tile * 128;
    const size_t gbase = (size_t)bh * L_ * D_;

    // ---- load q tile, scale, bf16 split, sqn via shfl ----
    {
        const int r = t >> 2, c0w = (t & 3) * 8;
        const float4* src = (const float4*)(qg + gbase + (size_t)(l0 + r)*D_ + (t & 3)*16);
        float ss = 0.f;
#pragma unroll
        for (int i = 0; i < 4; i++) {
            float4 x = src[i];
            x.x *= NORMV; x.y *= NORMV; x.z *= NORMV; x.w *= NORMV;
            ss += x.x*x.x + x.y*x.y + x.z*x.z + x.w*x.w;
            u32 h01, l01, h23, l23;
            bsplit2(x.x, x.y, h01, l01);
            bsplit2(x.z, x.w, h23, l23);
            *(uint2*)(smw + QHB2_W + r*BSTR + c0w + 2*i) = make_uint2(h01, h23);
            *(uint2*)(smw + QLB2_W + r*BSTR + c0w + 2*i) = make_uint2(l01, l23);
        }
        ss += __shfl_xor_sync(0xffffffffu, ss, 1);
        ss += __shfl_xor_sync(0xffffffffu, ss, 2);
        if ((lane & 3) == 0) smf[SQN2_F + r] = 0.5f * ss;
    }
    if (t < M_) smf[KSM2_F + t] = g_ksum[bh*M_ + t];

    // warp roles
    const int lbase = (w & 3) * 32;            // GEMM1 l-tile
    const int ng16 = (w >> 2) * 16;            // GEMM1 m-local base (within quarter)
    const int r0 = (w & 7) * 16;               // GEMM2 l-tile
    const int colbase = (w >> 3) * 32;         // GEMM2 d-range

    float acc2[4][4];
#pragma unroll
    for (int nt = 0; nt < 4; nt++)
#pragma unroll
        for (int i = 0; i < 4; i++) acc2[nt][i] = 0.f;
    float zacc[2][2] = {{0.f, 0.f}, {0.f, 0.f}};

    for (int mq = 0; mq < 4; mq++) {
        __syncthreads();   // (A) prior G2 done; first iter: q/ksum visible
        // load Pq (bf16 hi/lo) and KVq for this quarter
        {
            const uint4* sh = (const uint4*)g_Pbh + mq * 512;
            const uint4* sl = (const uint4*)g_Pbl + mq * 512;
            int m = t >> 3, j = t & 7;          // 512 threads = 512 uint4
            *(uint4*)(smw + PQH_W + m*BSTR + j*4) = sh[t];
            *(uint4*)(smw + PQL_W + m*BSTR + j*4) = sl[t];
        }
        {
            const float4* src = (const float4*)(g_kv + (size_t)bh * M_ * D_ + mq * 64 * D_);
#pragma unroll
            for (int i = 0; i < 2; i++) {
                int id = t + i * NT;            // 1024 float4
                int m = id >> 4, c4 = id & 15;
                *(float4*)(smf + KVQ_F + m*KVQ_STR + c4*4) = src[id];
            }
        }
        __syncthreads();   // (B) Pq/KVq visible

        // ---- GEMM1 quarter: proj[128 l][64 m], warp 32l x 16m ----
        float acc[2][2][4];
#pragma unroll
        for (int lt = 0; lt < 2; lt++)
#pragma unroll
            for (int nt = 0; nt < 2; nt++)
#pragma unroll
                for (int i = 0; i < 4; i++) acc[lt][nt][i] = 0.f;

#pragma unroll
        for (int ks = 0; ks < 4; ks++) {
            const int k0w = ks * 8;
#pragma unroll
            for (int lt = 0; lt < 2; lt++) {
                const int base = (lbase + lt*16 + g)*BSTR + k0w + tig;
                u32 ah[4], al[4];
                ah[0] = smw[QHB2_W + base];
                ah[1] = smw[QHB2_W + base + 8*BSTR];
                ah[2] = smw[QHB2_W + base + 4];
                ah[3] = smw[QHB2_W + base + 8*BSTR + 4];
                al[0] = smw[QLB2_W + base];
                al[1] = smw[QLB2_W + base + 8*BSTR];
                al[2] = smw[QLB2_W + base + 4];
                al[3] = smw[QLB2_W + base + 8*BSTR + 4];
#pragma unroll
                for (int nt = 0; nt < 2; nt++) {
                    const int bb = (ng16 + nt*8 + g)*BSTR + k0w + tig;
                    u32 bh0 = smw[PQH_W + bb];
                    u32 bh1 = smw[PQH_W + bb + 4];
                    u32 bl0 = smw[PQL_W + bb];
                    u32 bl1 = smw[PQL_W + bb + 4];
                    mma16(acc[lt][nt], ah, bh0, bh1);
                    mma16(acc[lt][nt], ah, bl0, bl1);
                    mma16(acc[lt][nt], al, bh0, bh1);
                }
            }
        }

        // ---- Epilogue quarter: exp, z-accum (regs), store QPq ----
#pragma unroll
        for (int lt = 0; lt < 2; lt++) {
            const int r1 = lbase + lt*16 + g;
            const int r2 = r1 + 8;
            const float sq1 = smf[SQN2_F + r1], sq2 = smf[SQN2_F + r2];
#pragma unroll
            for (int nt = 0; nt < 2; nt++) {
                const int n = ng16 + nt*8 + 2*tig;
                const int gm = mq*64 + n;
                const float ks0 = smf[KSM2_F + gm], ks1 = smf[KSM2_F + gm + 1];
                float e00 = __expf(acc[lt][nt][0] - sq1 + EPSK);
                float e01 = __expf(acc[lt][nt][1] - sq1 + EPSK);
                float e10 = __expf(acc[lt][nt][2] - sq2 + EPSK);
                float e11 = __expf(acc[lt][nt][3] - sq2 + EPSK);
                zacc[lt][0] += e00*ks0 + e01*ks1;
                zacc[lt][1] += e10*ks0 + e11*ks1;
                *(float2*)(smf + QPQ_F + r1*QPQ_STR + n) = make_float2(tf32r(e00), tf32r(e01));
                *(float2*)(smf + QPQ_F + r2*QPQ_STR + n) = make_float2(tf32r(e10), tf32r(e11));
            }
        }
        __syncthreads();   // (D) QPq visible

        // ---- GEMM2 quarter: out += QPq[128,64] @ KVq[64,64] ----
        for (int km = 0; km < 8; km++) {
            const int m0 = km * 8;
            u32 a[4];
            a[0] = f2u(smf[QPQ_F + (r0+g)*QPQ_STR + m0 + tig]);
            a[1] = f2u(smf[QPQ_F + (r0+8+g)*QPQ_STR + m0 + tig]);
            a[2] = f2u(smf[QPQ_F + (r0+g)*QPQ_STR + m0 + tig + 4]);
            a[3] = f2u(smf[QPQ_F + (r0+8+g)*QPQ_STR + m0 + tig + 4]);
#pragma unroll
            for (int nt = 0; nt < 4; nt++) {
                u32 b0 = f2u(smf[KVQ_F + (m0+tig)*KVQ_STR + colbase + nt*8 + g]);
                u32 b1 = f2u(smf[KVQ_F + (m0+tig+4)*KVQ_STR + colbase + nt*8 + g]);
                mma8(acc2[nt], a, b0, b1);
            }
        }
    }

    // ---- z partials to smem ----
#pragma unroll
    for (int lt = 0; lt < 2; lt++) {
        const int r1 = lbase + lt*16 + g;
        float z1 = zacc[lt][0], z2 = zacc[lt][1];
        z1 += __shfl_xor_sync(0xffffffffu, z1, 1);
        z1 += __shfl_xor_sync(0xffffffffu, z1, 2);
        z2 += __shfl_xor_sync(0xffffffffu, z2, 1);
        z2 += __shfl_xor_sync(0xffffffffu, z2, 2);
        if (tig == 0) {
            float* zp = smf + ZP2_F + (w >> 2) * 128;
            zp[r1] = z1;
            zp[r1 + 8] = z2;
        }
    }
    __syncthreads();

    // ---- Epilogue 2: scale by z (sum of 4 group partials), store ----
    {
        const float* zp = smf + ZP2_F;
        const int ra = r0 + g, rb = ra + 8;
        const float z1 = 1.0f / (zp[ra] + zp[128 + ra] + zp[256 + ra] + zp[384 + ra] + EPSZ);
        const float z2 = 1.0f / (zp[rb] + zp[128 + rb] + zp[256 + rb] + zp[384 + rb] + EPSZ);
        float* o1 = outg + gbase + (size_t)(l0 + ra)*D_ + colbase;
        float* o2 = outg + gbase + (size_t)(l0 + rb)*D_ + colbase;
#pragma unroll
        for (int nt = 0; nt < 4; nt++) {
            const int d = nt*8 + 2*tig;
            *(float2*)(o1 + d) = make_float2(acc2[nt][0]*z1, acc2[nt][1]*z1);
            *(float2*)(o2 + d) = make_float2(acc2[nt][2]*z2, acc2[nt][3]*z2);
        }
    }
}

extern "C" void kernel_launch(void* const* d_in, const int* in_sizes, int n_in,
                              void* d_out, int out_size) {
    (void)in_sizes; (void)n_in; (void)out_size;
    const float* q = (const float*)d_in[0];
    const float* k = (const float*)d_in[1];
    const float* v = (const float*)d_in[2];
    const float* P = (const float*)d_in[3];
    float* out = (float*)d_out;

    cudaFuncSetAttribute(k1_mma, cudaFuncAttributeMaxDynamicSharedMemorySize, K1_SMEM);
    cudaFuncSetAttribute(k2_out, cudaFuncAttributeMaxDynamicSharedMemorySize, K2_SMEM);

    k_prep_P<<<32, 256>>>(P);
    k1_mma<<<BH_*CH2, NT, K1_SMEM>>>(k, v);
    k_reduce<<<1056, 256>>>();
    k2_out<<<BH_*CH2, NT, K2_SMEM>>>(q, out);
}

// round 16
// speedup vs baseline: 1.1680x; 1.0764x over previous
#include <cuda_runtime.h>
#include <cuda_bf16.h>
#include <cuda_fp16.h>
#include <cstdint>

typedef unsigned int u32;

#define B_ 4
#define H_ 8
#define L_ 8192
#define D_ 64
#define M_ 256
#define BH_ (B_*H_)
#define CH2 64                              // 64 chunks of 128 l-rows
#define NORMV 0.35355339059327373f          // 64^(-1/4)
#define EPSK 1e-6f
#define EPSZ 1e-6f
#define NT 512
#define PSC 0.03125f                        // k1 partial scale 1/32 (exact)
#define QPS 0.0009765625f                   // qp fp16 scale 2^-10
#define OSC 65536.0f                        // out rescale 2^16

__device__ __align__(16) __half g_parth[BH_*CH2*M_*D_];   // 64 MB fp16 kv partials [m][d]
__device__ __align__(16) float g_kspart[BH_*CH2*M_];      // 2 MB fp32 ksum partials
__device__ __align__(16) __half g_kvT[BH_*D_*M_];         // kv^T fp16, scaled 2^-6
__device__ __align__(16) float g_ksum[BH_*M_];            // fp32
__device__ __align__(16) u32 g_Pbh[M_*D_/2];              // bf16-hi pairs
__device__ __align__(16) u32 g_Pbl[M_*D_/2];              // bf16-lo pairs

// ---- tf32 / bf16 / mma helpers ----
__device__ __forceinline__ float tf32r(float x) {
    u32 u; asm("cvt.rna.tf32.f32 %0, %1;" : "=r"(u) : "f"(x));
    return __uint_as_float(u);
}
__device__ __forceinline__ u32 f2u(float x) { return __float_as_uint(x); }
__device__ __forceinline__ u32 bpack(__nv_bfloat16 a, __nv_bfloat16 b) {
    unsigned short ua = *(unsigned short*)&a, ub = *(unsigned short*)&b;
    return (u32)ua | ((u32)ub << 16);
}
__device__ __forceinline__ void bsplit2(float a, float b, u32 &hi, u32 &lo) {
    __nv_bfloat16 ha = __float2bfloat16(a), hb = __float2bfloat16(b);
    float ra = a - __bfloat162float(ha);
    float rb = b - __bfloat162float(hb);
    hi = bpack(ha, hb);
    lo = bpack(__float2bfloat16(ra), __float2bfloat16(rb));
}
__device__ __forceinline__ void mma8(float* c, const u32* a, u32 b0, u32 b1) {
    asm volatile(
        "mma.sync.aligned.m16n8k8.row.col.f32.tf32.tf32.f32 "
        "{%0,%1,%2,%3}, {%4,%5,%6,%7}, {%8,%9}, {%0,%1,%2,%3};"
        : "+f"(c[0]), "+f"(c[1]), "+f"(c[2]), "+f"(c[3])
        : "r"(a[0]), "r"(a[1]), "r"(a[2]), "r"(a[3]), "r"(b0), "r"(b1));
}
__device__ __forceinline__ void mma16(float* c, const u32* a, u32 b0, u32 b1) {
    asm volatile(
        "mma.sync.aligned.m16n8k16.row.col.f32.bf16.bf16.f32 "
        "{%0,%1,%2,%3}, {%4,%5,%6,%7}, {%8,%9}, {%0,%1,%2,%3};"
        : "+f"(c[0]), "+f"(c[1]), "+f"(c[2]), "+f"(c[3])
        : "r"(a[0]), "r"(a[1]), "r"(a[2]), "r"(a[3]), "r"(b0), "r"(b1));
}
__device__ __forceinline__ void mma16h(float* c, const u32* a, u32 b0, u32 b1) {
    asm volatile(
        "mma.sync.aligned.m16n8k16.row.col.f32.f16.f16.f32 "
        "{%0,%1,%2,%3}, {%4,%5,%6,%7}, {%8,%9}, {%0,%1,%2,%3};"
        : "+f"(c[0]), "+f"(c[1]), "+f"(c[2]), "+f"(c[3])
        : "r"(a[0]), "r"(a[1]), "r"(a[2]), "r"(a[3]), "r"(b0), "r"(b1));
}

// ========== prep: P -> bf16 hi/lo split pairs ==========

__global__ void k_prep_P(const float* __restrict__ Pg) {
    int idx = blockIdx.x * 256 + threadIdx.x;   // 8192 pairs
    float x0 = Pg[2*idx], x1 = Pg[2*idx + 1];
    u32 hi, lo;
    bsplit2(x0, x1, hi, lo);
    g_Pbh[idx] = hi;
    g_Pbl[idx] = lo;
}

// ============================ k1: bf16-GEMM1 + tf32-GEMM2 (R14/15, proven) ============================
#define KHB_W  0
#define KLB_W  4608
#define PHB_W  9216
#define PLB_W  18432
#define QPT_F  0
#define V_F    33792
#define SQN1_F 43008
#define PKS_F  43136
#define K1_FLOATS 44160
#define K1_SMEM (K1_FLOATS*4)
#define BSTR 36
#define QPT_STR 132
#define VSTR 72

__global__ void __launch_bounds__(NT, 1)
k1_mma(const float* __restrict__ kg, const float* __restrict__ vg) {
    extern __shared__ float smf[];
    u32* smw = (u32*)smf;
    const int t = threadIdx.x;
    const int lane = t & 31, w = t >> 5;      // 16 warps
    const int g = lane >> 2, tig = lane & 3;
    const int bh = blockIdx.x >> 6, tile = blockIdx.x & 63;
    const int l0 = tile * 128;
    const size_t gbase = (size_t)bh * L_ * D_;

    {
        const uint4* sh = (const uint4*)g_Pbh;   // 2048 uint4
        const uint4* sl = (const uint4*)g_Pbl;
#pragma unroll
        for (int i = 0; i < 4; i++) {
            int id = t + i * NT;
            int m = id >> 3, j = id & 7;
            *(uint4*)(smw + PHB_W + m*BSTR + j*4) = sh[id];
            *(uint4*)(smw + PLB_W + m*BSTR + j*4) = sl[id];
        }
    }
    {
        const int r = t >> 2, c0w = (t & 3) * 8;
        const float4* src = (const float4*)(kg + gbase + (size_t)(l0 + r)*D_ + (t & 3)*16);
        float ss = 0.f;
#pragma unroll
        for (int i = 0; i < 4; i++) {
            float4 x = src[i];
            x.x *= NORMV; x.y *= NORMV; x.z *= NORMV; x.w *= NORMV;
            ss += x.x*x.x + x.y*x.y + x.z*x.z + x.w*x.w;
            u32 h01, l01, h23, l23;
            bsplit2(x.x, x.y, h01, l01);
            bsplit2(x.z, x.w, h23, l23);
            *(uint2*)(smw + KHB_W + r*BSTR + c0w + 2*i) = make_uint2(h01, h23);
            *(uint2*)(smw + KLB_W + r*BSTR + c0w + 2*i) = make_uint2(l01, l23);
        }
        ss += __shfl_xor_sync(0xffffffffu, ss, 1);
        ss += __shfl_xor_sync(0xffffffffu, ss, 2);
        if ((lane & 3) == 0) smf[SQN1_F + r] = 0.5f * ss;
    }
    {
        const float4* src = (const float4*)(vg + gbase + (size_t)l0*D_);
#pragma unroll
        for (int i = 0; i < 4; i++) {
            int id = t + i * NT;               // 2048 float4
            int l = id >> 4, c4 = id & 15;
            float4 x = src[id];
            x.x = tf32r(x.x); x.y = tf32r(x.y); x.z = tf32r(x.z); x.w = tf32r(x.w);
            *(float4*)(smf + V_F + l*VSTR + c4*4) = x;
        }
    }
    __syncthreads();

    const int lbase = (w & 3) * 32;
    const int n0base = (w >> 2) * 64;
    float acc[2][8][4];
#pragma unroll
    for (int lt = 0; lt < 2; lt++)
#pragma unroll
        for (int nt = 0; nt < 8; nt++)
#pragma unroll
            for (int i = 0; i < 4; i++) acc[lt][nt][i] = 0.f;

#pragma unroll
    for (int ks = 0; ks < 4; ks++) {
        const int k0w = ks * 8;
        u32 ah[2][4], al[2][4];
#pragma unroll
        for (int lt = 0; lt < 2; lt++) {
            const int base = (lbase + lt*16 + g)*BSTR + k0w + tig;
            ah[lt][0] = smw[KHB_W + base];
            ah[lt][1] = smw[KHB_W + base + 8*BSTR];
            ah[lt][2] = smw[KHB_W + base + 4];
            ah[lt][3] = smw[KHB_W + base + 8*BSTR + 4];
            al[lt][0] = smw[KLB_W + base];
            al[lt][1] = smw[KLB_W + base + 8*BSTR];
            al[lt][2] = smw[KLB_W + base + 4];
            al[lt][3] = smw[KLB_W + base + 8*BSTR + 4];
        }
#pragma unroll
        for (int nt = 0; nt < 8; nt++) {
            const int bb = (n0base + nt*8 + g)*BSTR + k0w + tig;
            u32 bh0 = smw[PHB_W + bb];
            u32 bh1 = smw[PHB_W + bb + 4];
            u32 bl0 = smw[PLB_W + bb];
            u32 bl1 = smw[PLB_W + bb + 4];
#pragma unroll
            for (int lt = 0; lt < 2; lt++) {
                mma16(acc[lt][nt], ah[lt], bh0, bh1);
                mma16(acc[lt][nt], ah[lt], bl0, bl1);
                mma16(acc[lt][nt], al[lt], bh0, bh1);
            }
        }
    }
    __syncthreads();

    {
        float sqa[2][2];
#pragma unroll
        for (int lt = 0; lt < 2; lt++) {
            const int r1 = lbase + lt*16 + g;
            sqa[lt][0] = smf[SQN1_F + r1];
            sqa[lt][1] = smf[SQN1_F + r1 + 8];
        }
#pragma unroll
        for (int nt = 0; nt < 8; nt++) {
            const int n = n0base + nt*8 + 2*tig;
            float cs0 = 0.f, cs1 = 0.f;
#pragma unroll
            for (int lt = 0; lt < 2; lt++) {
                const int r1 = lbase + lt*16 + g;
                const int r2 = r1 + 8;
                float e00 = __expf(acc[lt][nt][0] - sqa[lt][0] + EPSK);
                float e01 = __expf(acc[lt][nt][1] - sqa[lt][0] + EPSK);
                float e10 = __expf(acc[lt][nt][2] - sqa[lt][1] + EPSK);
                float e11 = __expf(acc[lt][nt][3] - sqa[lt][1] + EPSK);
                cs0 += e00 + e10;
                cs1 += e01 + e11;
                smf[QPT_F + n*QPT_STR + r1]     = tf32r(e00);
                smf[QPT_F + (n+1)*QPT_STR + r1] = tf32r(e01);
                smf[QPT_F + n*QPT_STR + r2]     = tf32r(e10);
                smf[QPT_F + (n+1)*QPT_STR + r2] = tf32r(e11);
            }
            cs0 += __shfl_xor_sync(0xffffffffu, cs0, 4);
            cs0 += __shfl_xor_sync(0xffffffffu, cs0, 8);
            cs0 += __shfl_xor_sync(0xffffffffu, cs0, 16);
            cs1 += __shfl_xor_sync(0xffffffffu, cs1, 4);
            cs1 += __shfl_xor_sync(0xffffffffu, cs1, 8);
            cs1 += __shfl_xor_sync(0xffffffffu, cs1, 16);
            if (lane < 4) {
                smf[PKS_F + w*64 + nt*8 + 2*tig]     = cs0;
                smf[PKS_F + w*64 + nt*8 + 2*tig + 1] = cs1;
            }
        }
    }
    __syncthreads();

    const int m0 = w * 16;
    float acc2[8][4];
#pragma unroll
    for (int nt = 0; nt < 8; nt++)
#pragma unroll
        for (int i = 0; i < 4; i++) acc2[nt][i] = 0.f;

    for (int k8 = 0; k8 < 16; k8++) {
        const int lk = k8 * 8;
        u32 a[4];
        a[0] = f2u(smf[QPT_F + (m0+g)*QPT_STR + lk + tig]);
        a[1] = f2u(smf[QPT_F + (m0+8+g)*QPT_STR + lk + tig]);
        a[2] = f2u(smf[QPT_F + (m0+g)*QPT_STR + lk + tig + 4]);
        a[3] = f2u(smf[QPT_F + (m0+8+g)*QPT_STR + lk + tig + 4]);
#pragma unroll
        for (int nt = 0; nt < 8; nt++) {
            u32 b0 = f2u(smf[V_F + (lk+tig)*VSTR + nt*8 + g]);
            u32 b1 = f2u(smf[V_F + (lk+tig+4)*VSTR + nt*8 + g]);
            mma8(acc2[nt], a, b0, b1);
        }
    }

    __half* pb = g_parth + (size_t)(bh*CH2 + tile) * (M_*D_);
    {
        const int r1 = m0 + g, r2 = r1 + 8;
#pragma unroll
        for (int nt = 0; nt < 8; nt++) {
            const int d = nt*8 + 2*tig;
            *(__half2*)(pb + r1*D_ + d) =
                __floats2half2_rn(acc2[nt][0]*PSC, acc2[nt][1]*PSC);
            *(__half2*)(pb + r2*D_ + d) =
                __floats2half2_rn(acc2[nt][2]*PSC, acc2[nt][3]*PSC);
        }
    }
    if (t < M_) {
        const int wb = (t >> 6) * 4, nloc = t & 63;
        float s = smf[PKS_F + (wb+0)*64 + nloc]
                + smf[PKS_F + (wb+1)*64 + nloc]
                + smf[PKS_F + (wb+2)*64 + nloc]
                + smf[PKS_F + (wb+3)*64 + nloc];
        g_kspart[(size_t)(bh*CH2 + tile)*M_ + t] = s;
    }
}

// ===== reduce: fp16 partials -> kv^T fp16 (x2^-6) via smem transpose; ksum fp32 =====

__global__ void k_reduce() {
    const int bid = blockIdx.x, t = threadIdx.x;
    if (bid < 256) {
        __shared__ float tile[32][66];
        const int bh = bid >> 3, mc = bid & 7;      // m-chunk of 32
        const int ml = t >> 3, d4 = (t & 7) * 4;    // half2 col index (d4*2 = d)
        const __half2* p = (const __half2*)g_parth
            + (size_t)bh * CH2 * 8192 + (size_t)(mc*32 + ml) * 32 + d4;
        float s[8];
#pragma unroll
        for (int i = 0; i < 8; i++) s[i] = 0.f;
        for (int c = 0; c < CH2; c++) {
            const __half2* pc = p + (size_t)c * 8192;
#pragma unroll
            for (int i = 0; i < 4; i++) {
                float2 f = __half22float2(pc[i]);
                s[2*i] += f.x; s[2*i+1] += f.y;
            }
        }
#pragma unroll
        for (int i = 0; i < 8; i++) tile[ml][d4*2 + i] = s[i];
        __syncthreads();
        // transposed write: thread (d = t>>2, m8 = (t&3)*8); scale 32 * 2^-6 = 0.5
        const int d = t >> 2, m8 = (t & 3) * 8;
        __half2 o[4];
#pragma unroll
        for (int i = 0; i < 4; i++)
            o[i] = __floats2half2_rn(tile[m8 + 2*i][d] * 0.5f,
                                     tile[m8 + 2*i + 1][d] * 0.5f);
        *(uint4*)(g_kvT + (size_t)bh*D_*M_ + d*M_ + mc*32 + m8) = *(uint4*)o;
    } else {
        int j = (bid - 256) * 256 + t;              // [0, 8192)
        int bh = j >> 8, n = j & 255;
        const float* p = g_kspart + (size_t)bh * CH2 * M_ + n;
        float s = 0.f;
#pragma unroll
        for (int c = 0; c < CH2; c++) s += p[(size_t)c * M_];
        g_ksum[bh*M_ + n] = s;
    }
}

// ====== k2: m-quartered, 2 CTAs/SM; bf16-GEMM1 + fp16-GEMM2 (86.5 KB smem) ======
// word offsets:
//  QHB@0 (4608) QLB@4608 (4608) PQH@9216 (2304) PQL@11520 (2304) -> 13824
//  QPH@13824 (128*36=4608 half rows stride 72h) -> 18432
//  KVT@18432 (64*36=2304) -> 20736
//  SQN@20736(128) KSUM@20864(256) ZP@21120(512) -> 21632 floats = 86528 B
#define QHB2_W 0
#define QLB2_W 4608
#define PQH_W  9216
#define PQL_W  11520
#define QPH_W  13824
#define KVT_W  18432
#define SQN2_F 20736
#define KSM2_F 20864
#define ZP2_F  21120
#define K2_FLOATS 21632
#define K2_SMEM (K2_FLOATS*4)
#define QPH_STRW 36
#define KVT_STRW 36

__global__ void __launch_bounds__(NT, 2)
k2_out(const float* __restrict__ qg, float* __restrict__ outg) {
    extern __shared__ float smf[];
    u32* smw = (u32*)smf;
    const int t = threadIdx.x;
    const int lane = t & 31, w = t >> 5;      // 16 warps
    const int g = lane >> 2, tig = lane & 3;
    const int bh = blockIdx.x >> 6, tile = blockIdx.x & 63;
    const int l0 = tile * 128;
    const size_t gbase = (size_t)bh * L_ * D_;

    // ---- load q tile, scale, bf16 split, sqn via shfl ----
    {
        const int r = t >> 2, c0w = (t & 3) * 8;
        const float4* src = (const float4*)(qg + gbase + (size_t)(l0 + r)*D_ + (t & 3)*16);
        float ss = 0.f;
#pragma unroll
        for (int i = 0; i < 4; i++) {
            float4 x = src[i];
            x.x *= NORMV; x.y *= NORMV; x.z *= NORMV; x.w *= NORMV;
            ss += x.x*x.x + x.y*x.y + x.z*x.z + x.w*x.w;
            u32 h01, l01, h23, l23;
            bsplit2(x.x, x.y, h01, l01);
            bsplit2(x.z, x.w, h23, l23);
            *(uint2*)(smw + QHB2_W + r*BSTR + c0w + 2*i) = make_uint2(h01, h23);
            *(uint2*)(smw + QLB2_W + r*BSTR + c0w + 2*i) = make_uint2(l01, l23);
        }
        ss += __shfl_xor_sync(0xffffffffu, ss, 1);
        ss += __shfl_xor_sync(0xffffffffu, ss, 2);
        if ((lane & 3) == 0) smf[SQN2_F + r] = 0.5f * ss;
    }
    if (t < M_) smf[KSM2_F + t] = g_ksum[bh*M_ + t];

    // warp roles
    const int lbase = (w & 3) * 32;            // GEMM1 l-tile
    const int ng16 = (w >> 2) * 16;            // GEMM1 m-local base (within quarter)
    const int r0 = (w & 7) * 16;               // GEMM2 l-tile
    const int colbase = (w >> 3) * 32;         // GEMM2 d-range

    float acc2[4][4];
#pragma unroll
    for (int nt = 0; nt < 4; nt++)
#pragma unroll
        for (int i = 0; i < 4; i++) acc2[nt][i] = 0.f;
    float zacc[2][2] = {{0.f, 0.f}, {0.f, 0.f}};

    for (int mq = 0; mq < 4; mq++) {
        __syncthreads();   // (A) prior G2 done; first iter: q/ksum visible
        // load Pq (bf16 hi/lo)
        {
            const uint4* sh = (const uint4*)g_Pbh + mq * 512;
            const uint4* sl = (const uint4*)g_Pbl + mq * 512;
            int m = t >> 3, j = t & 7;
            *(uint4*)(smw + PQH_W + m*BSTR + j*4) = sh[t];
            *(uint4*)(smw + PQL_W + m*BSTR + j*4) = sl[t];
        }
        // load kvT quarter (fp16, [d][m-chunk]) — 4096 halves = 512 uint4
        {
            const __half* src = g_kvT + (size_t)bh * D_ * M_ + mq * 64;
            const int d = t >> 3, j8 = (t & 7) * 8;      // 8 halves per thread
            uint4 v = *(const uint4*)(src + (size_t)d * M_ + j8);
            *(uint4*)(smw + KVT_W + d*KVT_STRW + (j8 >> 1)) = v;
        }
        __syncthreads();   // (B) Pq/KVT visible

        // ---- GEMM1 quarter: proj[128 l][64 m], warp 32l x 16m ----
        float acc[2][2][4];
#pragma unroll
        for (int lt = 0; lt < 2; lt++)
#pragma unroll
            for (int nt = 0; nt < 2; nt++)
#pragma unroll
                for (int i = 0; i < 4; i++) acc[lt][nt][i] = 0.f;

#pragma unroll
        for (int ks = 0; ks < 4; ks++) {
            const int k0w = ks * 8;
#pragma unroll
            for (int lt = 0; lt < 2; lt++) {
                const int base = (lbase + lt*16 + g)*BSTR + k0w + tig;
                u32 ah[4], al[4];
                ah[0] = smw[QHB2_W + base];
                ah[1] = smw[QHB2_W + base + 8*BSTR];
                ah[2] = smw[QHB2_W + base + 4];
                ah[3] = smw[QHB2_W + base + 8*BSTR + 4];
                al[0] = smw[QLB2_W + base];
                al[1] = smw[QLB2_W + base + 8*BSTR];
                al[2] = smw[QLB2_W + base + 4];
                al[3] = smw[QLB2_W + base + 8*BSTR + 4];
#pragma unroll
                for (int nt = 0; nt < 2; nt++) {
                    const int bb = (ng16 + nt*8 + g)*BSTR + k0w + tig;
                    u32 bh0 = smw[PQH_W + bb];
                    u32 bh1 = smw[PQH_W + bb + 4];
                    u32 bl0 = smw[PQL_W + bb];
                    u32 bl1 = smw[PQL_W + bb + 4];
                    mma16(acc[lt][nt], ah, bh0, bh1);
                    mma16(acc[lt][nt], ah, bl0, bl1);
                    mma16(acc[lt][nt], al, bh0, bh1);
                }
            }
        }

        // ---- Epilogue quarter: exp, z-accum (regs), store qp as scaled fp16 ----
        __half2* qph = (__half2*)(smw + QPH_W);
#pragma unroll
        for (int lt = 0; lt < 2; lt++) {
            const int r1 = lbase + lt*16 + g;
            const int r2 = r1 + 8;
            const float sq1 = smf[SQN2_F + r1], sq2 = smf[SQN2_F + r2];
#pragma unroll
            for (int nt = 0; nt < 2; nt++) {
                const int n = ng16 + nt*8 + 2*tig;
                const int gm = mq*64 + n;
                const float ks0 = smf[KSM2_F + gm], ks1 = smf[KSM2_F + gm + 1];
                float e00 = __expf(acc[lt][nt][0] - sq1 + EPSK);
                float e01 = __expf(acc[lt][nt][1] - sq1 + EPSK);
                float e10 = __expf(acc[lt][nt][2] - sq2 + EPSK);
                float e11 = __expf(acc[lt][nt][3] - sq2 + EPSK);
                zacc[lt][0] += e00*ks0 + e01*ks1;
                zacc[lt][1] += e10*ks0 + e11*ks1;
                qph[r1*QPH_STRW + (n >> 1)] = __floats2half2_rn(e00*QPS, e01*QPS);
                qph[r2*QPH_STRW + (n >> 1)] = __floats2half2_rn(e10*QPS, e11*QPS);
            }
        }
        __syncthreads();   // (D) qp_h visible

        // ---- GEMM2 quarter (fp16 k16): out += qp_h[128,64] @ kvT_h^T ----
#pragma unroll
        for (int ks = 0; ks < 4; ks++) {
            const int k0w = ks * 8;                // 16 halves = 8 words
            u32 a[4];
            a[0] = smw[QPH_W + (r0+g)*QPH_STRW + k0w + tig];
            a[1] = smw[QPH_W + (r0+8+g)*QPH_STRW + k0w + tig];
            a[2] = smw[QPH_W + (r0+g)*QPH_STRW + k0w + 4 + tig];
            a[3] = smw[QPH_W + (r0+8+g)*QPH_STRW + k0w + 4 + tig];
#pragma unroll
            for (int nt = 0; nt < 4; nt++) {
                const int d = colbase + nt*8 + g;
                u32 b0 = smw[KVT_W + d*KVT_STRW + k0w + tig];
                u32 b1 = smw[KVT_W + d*KVT_STRW + k0w + 4 + tig];
                mma16h(acc2[nt], a, b0, b1);
            }
        }
    }

    // ---- z partials to smem ----
#pragma unroll
    for (int lt = 0; lt < 2; lt++) {
        const int r1 = lbase + lt*16 + g;
        float z1 = zacc[lt][0], z2 = zacc[lt][1];
        z1 += __shfl_xor_sync(0xffffffffu, z1, 1);
        z1 += __shfl_xor_sync(0xffffffffu, z1, 2);
        z2 += __shfl_xor_sync(0xffffffffu, z2, 1);
        z2 += __shfl_xor_sync(0xffffffffu, z2, 2);
        if (tig == 0) {
            float* zp = smf + ZP2_F + (w >> 2) * 128;
            zp[r1] = z1;
            zp[r1 + 8] = z2;
        }
    }
    __syncthreads();

    // ---- Epilogue 2: scale by z * 2^16, store ----
    {
        const float* zp = smf + ZP2_F;
        const int ra = r0 + g, rb = ra + 8;
        const float z1 = OSC / (zp[ra] + zp[128 + ra] + zp[256 + ra] + zp[384 + ra] + EPSZ);
        const float z2 = OSC / (zp[rb] + zp[128 + rb] + zp[256 + rb] + zp[384 + rb] + EPSZ);
        float* o1 = outg + gbase + (size_t)(l0 + ra)*D_ + colbase;
        float* o2 = outg + gbase + (size_t)(l0 + rb)*D_ + colbase;
#pragma unroll
        for (int nt = 0; nt < 4; nt++) {
            const int d = nt*8 + 2*tig;
            *(float2*)(o1 + d) = make_float2(acc2[nt][0]*z1, acc2[nt][1]*z1);
            *(float2*)(o2 + d) = make_float2(acc2[nt][2]*z2, acc2[nt][3]*z2);
        }
    }
}

extern "C" void kernel_launch(void* const* d_in, const int* in_sizes, int n_in,
                              void* d_out, int out_size) {
    (void)in_sizes; (void)n_in; (void)out_size;
    const float* q = (const float*)d_in[0];
    const float* k = (const float*)d_in[1];
    const float* v = (const float*)d_in[2];
    const float* P = (const float*)d_in[3];
    float* out = (float*)d_out;

    cudaFuncSetAttribute(k1_mma, cudaFuncAttributeMaxDynamicSharedMemorySize, K1_SMEM);
    cudaFuncSetAttribute(k2_out, cudaFuncAttributeMaxDynamicSharedMemorySize, K2_SMEM);

    k_prep_P<<<32, 256>>>(P);
    k1_mma<<<BH_*CH2, NT, K1_SMEM>>>(k, v);
    k_reduce<<<288, 256>>>();
    k2_out<<<BH_*CH2, NT, K2_SMEM>>>(q, out);
}

// round 17
// speedup vs baseline: 1.1689x; 1.0008x over previous
#include <cuda_runtime.h>
#include <cuda_bf16.h>
#include <cuda_fp16.h>
#include <cstdint>

typedef unsigned int u32;

#define B_ 4
#define H_ 8
#define L_ 8192
#define D_ 64
#define M_ 256
#define BH_ (B_*H_)
#define CH2 64                              // 64 chunks of 128 l-rows
#define NORMV 0.35355339059327373f          // 64^(-1/4)
#define EPSK 1e-6f
#define EPSZ 1e-6f
#define NT 512
#define QPS 0.0009765625f                   // qp fp16 scale 2^-10
#define OSC 65536.0f                        // k2 out rescale 2^16
#define PRS 32.0f                           // k1 partial rescale 2^5 (net = 2^-5, as R14)

__device__ __align__(16) __half g_parth[BH_*CH2*M_*D_];   // 64 MB fp16 kv partials [m][d], x2^-5
__device__ __align__(16) float g_kspart[BH_*CH2*M_];      // 2 MB fp32 ksum partials
__device__ __align__(16) __half g_kvT[BH_*D_*M_];         // kv^T fp16, scaled 2^-6
__device__ __align__(16) float g_ksum[BH_*M_];            // fp32
__device__ __align__(16) __half g_vT[BH_*D_*L_];          // v^T fp16 [bh][d][l], 32 MB
__device__ __align__(16) u32 g_Pbh[M_*D_/2];              // bf16-hi pairs
__device__ __align__(16) u32 g_Pbl[M_*D_/2];              // bf16-lo pairs

// ---- bf16 / mma helpers ----
__device__ __forceinline__ u32 bpack(__nv_bfloat16 a, __nv_bfloat16 b) {
    unsigned short ua = *(unsigned short*)&a, ub = *(unsigned short*)&b;
    return (u32)ua | ((u32)ub << 16);
}
__device__ __forceinline__ void bsplit2(float a, float b, u32 &hi, u32 &lo) {
    __nv_bfloat16 ha = __float2bfloat16(a), hb = __float2bfloat16(b);
    float ra = a - __bfloat162float(ha);
    float rb = b - __bfloat162float(hb);
    hi = bpack(ha, hb);
    lo = bpack(__float2bfloat16(ra), __float2bfloat16(rb));
}
__device__ __forceinline__ void mma16(float* c, const u32* a, u32 b0, u32 b1) {
    asm volatile(
        "mma.sync.aligned.m16n8k16.row.col.f32.bf16.bf16.f32 "
        "{%0,%1,%2,%3}, {%4,%5,%6,%7}, {%8,%9}, {%0,%1,%2,%3};"
        : "+f"(c[0]), "+f"(c[1]), "+f"(c[2]), "+f"(c[3])
        : "r"(a[0]), "r"(a[1]), "r"(a[2]), "r"(a[3]), "r"(b0), "r"(b1));
}
__device__ __forceinline__ void mma16h(float* c, const u32* a, u32 b0, u32 b1) {
    asm volatile(
        "mma.sync.aligned.m16n8k16.row.col.f32.f16.f16.f32 "
        "{%0,%1,%2,%3}, {%4,%5,%6,%7}, {%8,%9}, {%0,%1,%2,%3};"
        : "+f"(c[0]), "+f"(c[1]), "+f"(c[2]), "+f"(c[3])
        : "r"(a[0]), "r"(a[1]), "r"(a[2]), "r"(a[3]), "r"(b0), "r"(b1));
}

#define BSTR 36

// ========== prep: P -> bf16 hi/lo split pairs ==========

__global__ void k_prep_P(const float* __restrict__ Pg) {
    int idx = blockIdx.x * 256 + threadIdx.x;   // 8192 pairs
    float x0 = Pg[2*idx], x1 = Pg[2*idx + 1];
    u32 hi, lo;
    bsplit2(x0, x1, hi, lo);
    g_Pbh[idx] = hi;
    g_Pbl[idx] = lo;
}

// ========== prep: v [bh][l][d] fp32 -> g_vT [bh][d][l] fp16 ==========

__global__ void k_prep_v(const float* __restrict__ vg) {
    __shared__ float st[64*67];
    const int t = threadIdx.x;
    const int bh = blockIdx.x >> 7, lc = blockIdx.x & 127;
    const int l0 = lc * 64;
    const float4* src = (const float4*)(vg + (size_t)bh*L_*D_ + (size_t)l0*D_);
#pragma unroll
    for (int i = 0; i < 4; i++) {
        int id = t + i*256;
        int ll = id >> 4, c4 = id & 15;
        float4 x = src[id];
        float* p = st + ll*67 + c4*4;
        p[0] = x.x; p[1] = x.y; p[2] = x.z; p[3] = x.w;
    }
    __syncthreads();
    const int d = t >> 2, l8 = (t & 3) * 16;
    __half2 o[8];
#pragma unroll
    for (int i = 0; i < 8; i++)
        o[i] = __floats2half2_rn(st[(l8 + 2*i)*67 + d], st[(l8 + 2*i + 1)*67 + d]);
    __half* dst = g_vT + ((size_t)(bh*D_ + d))*L_ + l0 + l8;
    *(uint4*)(dst)     = *(uint4*)(o);
    *(uint4*)(dst + 8) = *(uint4*)(o + 4);
}

// ====== k1: m-quartered, 2 CTAs/SM; bf16-GEMM1 + fp16-GEMM2 (91.6 KB smem) ======
// word offsets:
//  KHB@0 (4608) KLB@4608 (4608) PQH1@9216 (2304) PQL1@11520 (2304) -> 13824
//  QPTQ@13824 (64 m x 68w) 4352 -> 18176
//  VT1@18176 (64 d x 68w) 4352 -> 22528
//  SQN1@22528(128) PKS@22656(256) -> 22912 words = 91648 B
#define KHB_W  0
#define KLB_W  4608
#define PQH1_W 9216
#define PQL1_W 11520
#define QPTQ_W 13824
#define VT1_W  18176
#define SQN1_F 22528
#define PKS_F  22656
#define K1_WORDS 22912
#define K1_SMEM (K1_WORDS*4)

__global__ void __launch_bounds__(NT, 2)
k1_mma(const float* __restrict__ kg) {
    extern __shared__ float smf[];
    u32* smw = (u32*)smf;
    __half* qph = (__half*)(smw + QPTQ_W);
    const int t = threadIdx.x;
    const int lane = t & 31, w = t >> 5;      // 16 warps
    const int g = lane >> 2, tig = lane & 3;
    const int bh = blockIdx.x >> 6, tile = blockIdx.x & 63;
    const int l0 = tile * 128;
    const size_t gbase = (size_t)bh * L_ * D_;

    // ---- load k tile, scale, bf16 split, sqn via shfl ----
    {
        const int r = t >> 2, c0w = (t & 3) * 8;
        const float4* src = (const float4*)(kg + gbase + (size_t)(l0 + r)*D_ + (t & 3)*16);
        float ss = 0.f;
#pragma unroll
        for (int i = 0; i < 4; i++) {
            float4 x = src[i];
            x.x *= NORMV; x.y *= NORMV; x.z *= NORMV; x.w *= NORMV;
            ss += x.x*x.x + x.y*x.y + x.z*x.z + x.w*x.w;
            u32 h01, l01, h23, l23;
            bsplit2(x.x, x.y, h01, l01);
            bsplit2(x.z, x.w, h23, l23);
            *(uint2*)(smw + KHB_W + r*BSTR + c0w + 2*i) = make_uint2(h01, h23);
            *(uint2*)(smw + KLB_W + r*BSTR + c0w + 2*i) = make_uint2(l01, l23);
        }
        ss += __shfl_xor_sync(0xffffffffu, ss, 1);
        ss += __shfl_xor_sync(0xffffffffu, ss, 2);
        if ((lane & 3) == 0) smf[SQN1_F + r] = 0.5f * ss;
    }
    // ---- load vT (fp16, [d][l0..l0+127]) once: 64 rows x 64 words ----
    {
        const int d = t >> 3, wj = (t & 7) * 8;
        const u32* srow = (const u32*)(g_vT + ((size_t)(bh*D_ + d))*L_ + l0);
        uint4 v0 = *(const uint4*)(srow + wj);
        uint4 v1 = *(const uint4*)(srow + wj + 4);
        *(uint4*)(smw + VT1_W + d*68 + wj)     = v0;
        *(uint4*)(smw + VT1_W + d*68 + wj + 4) = v1;
    }
    __syncthreads();

    const int lbase = (w & 3) * 32;            // GEMM1 l-tile
    const int ng16 = (w >> 2) * 16;            // GEMM1 m-local base
    const int mt16 = (w & 3) * 16;             // GEMM2 m-tile
    const int dg16 = (w >> 2) * 16;            // GEMM2 d-range
    float* pks = smf + PKS_F;

    for (int mq = 0; mq < 4; mq++) {
        if (mq) __syncthreads();               // (A) prev G2 + pks reads done
        {
            const uint4* sh = (const uint4*)g_Pbh + mq * 512;
            const uint4* sl = (const uint4*)g_Pbl + mq * 512;
            int m = t >> 3, j = t & 7;
            *(uint4*)(smw + PQH1_W + m*BSTR + j*4) = sh[t];
            *(uint4*)(smw + PQL1_W + m*BSTR + j*4) = sl[t];
        }
        __syncthreads();                       // (B) Pq visible

        // ---- GEMM1 quarter: proj[128 l][64 m], warp 32l x 16m ----
        float acc[2][2][4];
#pragma unroll
        for (int lt = 0; lt < 2; lt++)
#pragma unroll
            for (int nt = 0; nt < 2; nt++)
#pragma unroll
                for (int i = 0; i < 4; i++) acc[lt][nt][i] = 0.f;

#pragma unroll
        for (int ks = 0; ks < 4; ks++) {
            const int k0w = ks * 8;
#pragma unroll
            for (int lt = 0; lt < 2; lt++) {
                const int base = (lbase + lt*16 + g)*BSTR + k0w + tig;
                u32 ah[4], al[4];
                ah[0] = smw[KHB_W + base];
                ah[1] = smw[KHB_W + base + 8*BSTR];
                ah[2] = smw[KHB_W + base + 4];
                ah[3] = smw[KHB_W + base + 8*BSTR + 4];
                al[0] = smw[KLB_W + base];
                al[1] = smw[KLB_W + base + 8*BSTR];
                al[2] = smw[KLB_W + base + 4];
                al[3] = smw[KLB_W + base + 8*BSTR + 4];
#pragma unroll
                for (int nt = 0; nt < 2; nt++) {
                    const int bb = (ng16 + nt*8 + g)*BSTR + k0w + tig;
                    u32 bh0 = smw[PQH1_W + bb];
                    u32 bh1 = smw[PQH1_W + bb + 4];
                    u32 bl0 = smw[PQL1_W + bb];
                    u32 bl1 = smw[PQL1_W + bb + 4];
                    mma16(acc[lt][nt], ah, bh0, bh1);
                    mma16(acc[lt][nt], ah, bl0, bl1);
                    mma16(acc[lt][nt], al, bh0, bh1);
                }
            }
        }

        // ---- Epilogue quarter: exp, u16 transposed qpT_h store, ksum partials ----
        {
            float sqa[2][2];
#pragma unroll
            for (int lt = 0; lt < 2; lt++) {
                const int r1 = lbase + lt*16 + g;
                sqa[lt][0] = smf[SQN1_F + r1];
                sqa[lt][1] = smf[SQN1_F + r1 + 8];
            }
#pragma unroll
            for (int nt = 0; nt < 2; nt++) {
                const int n = ng16 + nt*8 + 2*tig;   // local m in [0,64)
                float cs0 = 0.f, cs1 = 0.f;
#pragma unroll
                for (int lt = 0; lt < 2; lt++) {
                    const int r1 = lbase + lt*16 + g;
                    const int r2 = r1 + 8;
                    float e00 = __expf(acc[lt][nt][0] - sqa[lt][0] + EPSK);
                    float e01 = __expf(acc[lt][nt][1] - sqa[lt][0] + EPSK);
                    float e10 = __expf(acc[lt][nt][2] - sqa[lt][1] + EPSK);
                    float e11 = __expf(acc[lt][nt][3] - sqa[lt][1] + EPSK);
                    cs0 += e00 + e10;
                    cs1 += e01 + e11;
                    qph[n*136 + r1]     = __float2half_rn(e00*QPS);
                    qph[(n+1)*136 + r1] = __float2half_rn(e01*QPS);
                    qph[n*136 + r2]     = __float2half_rn(e10*QPS);
                    qph[(n+1)*136 + r2] = __float2half_rn(e11*QPS);
                }
                cs0 += __shfl_xor_sync(0xffffffffu, cs0, 4);
                cs0 += __shfl_xor_sync(0xffffffffu, cs0, 8);
                cs0 += __shfl_xor_sync(0xffffffffu, cs0, 16);
                cs1 += __shfl_xor_sync(0xffffffffu, cs1, 4);
                cs1 += __shfl_xor_sync(0xffffffffu, cs1, 8);
                cs1 += __shfl_xor_sync(0xffffffffu, cs1, 16);
                if (lane < 4) {
                    pks[w*16 + nt*8 + 2*tig]     = cs0;
                    pks[w*16 + nt*8 + 2*tig + 1] = cs1;
                }
            }
        }
        __syncthreads();                       // (D) qpT_h + pks visible

        // ---- ksum combine for this quarter (threads < 64) ----
        if (t < 64) {
            const int wc = t >> 4, idx = t & 15;
            float s = pks[(wc*4+0)*16 + idx] + pks[(wc*4+1)*16 + idx]
                    + pks[(wc*4+2)*16 + idx] + pks[(wc*4+3)*16 + idx];
            g_kspart[(size_t)(bh*CH2 + tile)*M_ + mq*64 + t] = s;
        }

        // ---- GEMM2 quarter (fp16 k16): kv_q[64m,64d] = qpT_h @ vT_h^T ----
        float acc2[2][4];
#pragma unroll
        for (int nt = 0; nt < 2; nt++)
#pragma unroll
            for (int i = 0; i < 4; i++) acc2[nt][i] = 0.f;

#pragma unroll
        for (int ks = 0; ks < 8; ks++) {
            const int kw = ks * 8;
            u32 a[4];
            a[0] = smw[QPTQ_W + (mt16+g)*68 + kw + tig];
            a[1] = smw[QPTQ_W + (mt16+8+g)*68 + kw + tig];
            a[2] = smw[QPTQ_W + (mt16+g)*68 + kw + 4 + tig];
            a[3] = smw[QPTQ_W + (mt16+8+g)*68 + kw + 4 + tig];
#pragma unroll
            for (int nt = 0; nt < 2; nt++) {
                u32 b0 = smw[VT1_W + (dg16+nt*8+g)*68 + kw + tig];
                u32 b1 = smw[VT1_W + (dg16+nt*8+g)*68 + kw + 4 + tig];
                mma16h(acc2[nt], a, b0, b1);
            }
        }

        // ---- write kv partial (fp16, x2^-5 net) ----
        {
            __half* pb = g_parth + (size_t)(bh*CH2 + tile) * (M_*D_);
            const int r1 = mq*64 + mt16 + g, r2 = r1 + 8;
#pragma unroll
            for (int nt = 0; nt < 2; nt++) {
                const int d = dg16 + nt*8 + 2*tig;
                *(__half2*)(pb + r1*D_ + d) =
                    __floats2half2_rn(acc2[nt][0]*PRS, acc2[nt][1]*PRS);
                *(__half2*)(pb + r2*D_ + d) =
                    __floats2half2_rn(acc2[nt][2]*PRS, acc2[nt][3]*PRS);
            }
        }
    }
}

// ===== reduce: fp16 partials -> kv^T fp16 (x2^-6) via smem transpose; ksum fp32 =====

__global__ void k_reduce() {
    const int bid = blockIdx.x, t = threadIdx.x;
    if (bid < 256) {
        __shared__ float tile[32][66];
        const int bh = bid >> 3, mc = bid & 7;      // m-chunk of 32
        const int ml = t >> 3, d4 = (t & 7) * 4;    // half2 col index (d4*2 = d)
        const __half2* p = (const __half2*)g_parth
            + (size_t)bh * CH2 * 8192 + (size_t)(mc*32 + ml) * 32 + d4;
        float s[8];
#pragma unroll
        for (int i = 0; i < 8; i++) s[i] = 0.f;
        for (int c = 0; c < CH2; c++) {
            const __half2* pc = p + (size_t)c * 8192;
#pragma unroll
            for (int i = 0; i < 4; i++) {
                float2 f = __half22float2(pc[i]);
                s[2*i] += f.x; s[2*i+1] += f.y;
            }
        }
#pragma unroll
        for (int i = 0; i < 8; i++) tile[ml][d4*2 + i] = s[i];
        __syncthreads();
        // transposed write: thread (d = t>>2, m8 = (t&3)*8); scale 32 * 2^-6 = 0.5
        const int d = t >> 2, m8 = (t & 3) * 8;
        __half2 o[4];
#pragma unroll
        for (int i = 0; i < 4; i++)
            o[i] = __floats2half2_rn(tile[m8 + 2*i][d] * 0.5f,
                                     tile[m8 + 2*i + 1][d] * 0.5f);
        *(uint4*)(g_kvT + (size_t)bh*D_*M_ + d*M_ + mc*32 + m8) = *(uint4*)o;
    } else {
        int j = (bid - 256) * 256 + t;              // [0, 8192)
        int bh = j >> 8, n = j & 255;
        const float* p = g_kspart + (size_t)bh * CH2 * M_ + n;
        float s = 0.f;
#pragma unroll
        for (int c = 0; c < CH2; c++) s += p[(size_t)c * M_];
        g_ksum[bh*M_ + n] = s;
    }
}

// ====== k2: m-quartered, 2 CTAs/SM; bf16-GEMM1 + fp16-GEMM2 (R16, proven) ======
#define QHB2_W 0
#define QLB2_W 4608
#define PQH_W  9216
#define PQL_W  11520
#define QPH_W  13824
#define KVT_W  18432
#define SQN2_F 20736
#define KSM2_F 20864
#define ZP2_F  21120
#define K2_FLOATS 21632
#define K2_SMEM (K2_FLOATS*4)
#define QPH_STRW 36
#define KVT_STRW 36

__global__ void __launch_bounds__(NT, 2)
k2_out(const float* __restrict__ qg, float* __restrict__ outg) {
    extern __shared__ float smf[];
    u32* smw = (u32*)smf;
    const int t = threadIdx.x;
    const int lane = t & 31, w = t >> 5;      // 16 warps
    const int g = lane >> 2, tig = lane & 3;
    const int bh = blockIdx.x >> 6, tile = blockIdx.x & 63;
    const int l0 = tile * 128;
    const size_t gbase = (size_t)bh * L_ * D_;

    // ---- load q tile, scale, bf16 split, sqn via shfl ----
    {
        const int r = t >> 2, c0w = (t & 3) * 8;
        const float4* src = (const float4*)(qg + gbase + (size_t)(l0 + r)*D_ + (t & 3)*16);
        float ss = 0.f;
#pragma unroll
        for (int i = 0; i < 4; i++) {
            float4 x = src[i];
            x.x *= NORMV; x.y *= NORMV; x.z *= NORMV; x.w *= NORMV;
            ss += x.x*x.x + x.y*x.y + x.z*x.z + x.w*x.w;
            u32 h01, l01, h23, l23;
            bsplit2(x.x, x.y, h01, l01);
            bsplit2(x.z, x.w, h23, l23);
            *(uint2*)(smw + QHB2_W + r*BSTR + c0w + 2*i) = make_uint2(h01, h23);
            *(uint2*)(smw + QLB2_W + r*BSTR + c0w + 2*i) = make_uint2(l01, l23);
        }
        ss += __shfl_xor_sync(0xffffffffu, ss, 1);
        ss += __shfl_xor_sync(0xffffffffu, ss, 2);
        if ((lane & 3) == 0) smf[SQN2_F + r] = 0.5f * ss;
    }
    if (t < M_) smf[KSM2_F + t] = g_ksum[bh*M_ + t];

    const int lbase = (w & 3) * 32;
    const int ng16 = (w >> 2) * 16;
    const int r0 = (w & 7) * 16;
    const int colbase = (w >> 3) * 32;

    float acc2[4][4];
#pragma unroll
    for (int nt = 0; nt < 4; nt++)
#pragma unroll
        for (int i = 0; i < 4; i++) acc2[nt][i] = 0.f;
    float zacc[2][2] = {{0.f, 0.f}, {0.f, 0.f}};

    for (int mq = 0; mq < 4; mq++) {
        __syncthreads();   // (A)
        {
            const uint4* sh = (const uint4*)g_Pbh + mq * 512;
            const uint4* sl = (const uint4*)g_Pbl + mq * 512;
            int m = t >> 3, j = t & 7;
            *(uint4*)(smw + PQH_W + m*BSTR + j*4) = sh[t];
            *(uint4*)(smw + PQL_W + m*BSTR + j*4) = sl[t];
        }
        {
            const __half* src = g_kvT + (size_t)bh * D_ * M_ + mq * 64;
            const int d = t >> 3, j8 = (t & 7) * 8;
            uint4 v = *(const uint4*)(src + (size_t)d * M_ + j8);
            *(uint4*)(smw + KVT_W + d*KVT_STRW + (j8 >> 1)) = v;
        }
        __syncthreads();   // (B)

        float acc[2][2][4];
#pragma unroll
        for (int lt = 0; lt < 2; lt++)
#pragma unroll
            for (int nt = 0; nt < 2; nt++)
#pragma unroll
                for (int i = 0; i < 4; i++) acc[lt][nt][i] = 0.f;

#pragma unroll
        for (int ks = 0; ks < 4; ks++) {
            const int k0w = ks * 8;
#pragma unroll
            for (int lt = 0; lt < 2; lt++) {
                const int base = (lbase + lt*16 + g)*BSTR + k0w + tig;
                u32 ah[4], al[4];
                ah[0] = smw[QHB2_W + base];
                ah[1] = smw[QHB2_W + base + 8*BSTR];
                ah[2] = smw[QHB2_W + base + 4];
                ah[3] = smw[QHB2_W + base + 8*BSTR + 4];
                al[0] = smw[QLB2_W + base];
                al[1] = smw[QLB2_W + base + 8*BSTR];
                al[2] = smw[QLB2_W + base + 4];
                al[3] = smw[QLB2_W + base + 8*BSTR + 4];
#pragma unroll
                for (int nt = 0; nt < 2; nt++) {
                    const int bb = (ng16 + nt*8 + g)*BSTR + k0w + tig;
                    u32 bh0 = smw[PQH_W + bb];
                    u32 bh1 = smw[PQH_W + bb + 4];
                    u32 bl0 = smw[PQL_W + bb];
                    u32 bl1 = smw[PQL_W + bb + 4];
                    mma16(acc[lt][nt], ah, bh0, bh1);
                    mma16(acc[lt][nt], ah, bl0, bl1);
                    mma16(acc[lt][nt], al, bh0, bh1);
                }
            }
        }

        __half2* qphh = (__half2*)(smw + QPH_W);
#pragma unroll
        for (int lt = 0; lt < 2; lt++) {
            const int r1 = lbase + lt*16 + g;
            const int r2 = r1 + 8;
            const float sq1 = smf[SQN2_F + r1], sq2 = smf[SQN2_F + r2];
#pragma unroll
            for (int nt = 0; nt < 2; nt++) {
                const int n = ng16 + nt*8 + 2*tig;
                const int gm = mq*64 + n;
                const float ks0 = smf[KSM2_F + gm], ks1 = smf[KSM2_F + gm + 1];
                float e00 = __expf(acc[lt][nt][0] - sq1 + EPSK);
                float e01 = __expf(acc[lt][nt][1] - sq1 + EPSK);
                float e10 = __expf(acc[lt][nt][2] - sq2 + EPSK);
                float e11 = __expf(acc[lt][nt][3] - sq2 + EPSK);
                zacc[lt][0] += e00*ks0 + e01*ks1;
                zacc[lt][1] += e10*ks0 + e11*ks1;
                qphh[r1*QPH_STRW + (n >> 1)] = __floats2half2_rn(e00*QPS, e01*QPS);
                qphh[r2*QPH_STRW + (n >> 1)] = __floats2half2_rn(e10*QPS, e11*QPS);
            }
        }
        __syncthreads();   // (D)

#pragma unroll
        for (int ks = 0; ks < 4; ks++) {
            const int k0w = ks * 8;
            u32 a[4];
            a[0] = smw[QPH_W + (r0+g)*QPH_STRW + k0w + tig];
            a[1] = smw[QPH_W + (r0+8+g)*QPH_STRW + k0w + tig];
            a[2] = smw[QPH_W + (r0+g)*QPH_STRW + k0w + 4 + tig];
            a[3] = smw[QPH_W + (r0+8+g)*QPH_STRW + k0w + 4 + tig];
#pragma unroll
            for (int nt = 0; nt < 4; nt++) {
                const int d = colbase + nt*8 + g;
                u32 b0 = smw[KVT_W + d*KVT_STRW + k0w + tig];
                u32 b1 = smw[KVT_W + d*KVT_STRW + k0w + 4 + tig];
                mma16h(acc2[nt], a, b0, b1);
            }
        }
    }

#pragma unroll
    for (int lt = 0; lt < 2; lt++) {
        const int r1 = lbase + lt*16 + g;
        float z1 = zacc[lt][0], z2 = zacc[lt][1];
        z1 += __shfl_xor_sync(0xffffffffu, z1, 1);
        z1 += __shfl_xor_sync(0xffffffffu, z1, 2);
        z2 += __shfl_xor_sync(0xffffffffu, z2, 1);
        z2 += __shfl_xor_sync(0xffffffffu, z2, 2);
        if (tig == 0) {
            float* zp = smf + ZP2_F + (w >> 2) * 128;
            zp[r1] = z1;
            zp[r1 + 8] = z2;
        }
    }
    __syncthreads();

    {
        const float* zp = smf + ZP2_F;
        const int ra = r0 + g, rb = ra + 8;
        const float z1 = OSC / (zp[ra] + zp[128 + ra] + zp[256 + ra] + zp[384 + ra] + EPSZ);
        const float z2 = OSC / (zp[rb] + zp[128 + rb] + zp[256 + rb] + zp[384 + rb] + EPSZ);
        float* o1 = outg + gbase + (size_t)(l0 + ra)*D_ + colbase;
        float* o2 = outg + gbase + (size_t)(l0 + rb)*D_ + colbase;
#pragma unroll
        for (int nt = 0; nt < 4; nt++) {
            const int d = nt*8 + 2*tig;
            *(float2*)(o1 + d) = make_float2(acc2[nt][0]*z1, acc2[nt][1]*z1);
            *(float2*)(o2 + d) = make_float2(acc2[nt][2]*z2, acc2[nt][3]*z2);
        }
    }
}

extern "C" void kernel_launch(void* const* d_in, const int* in_sizes, int n_in,
                              void* d_out, int out_size) {
    (void)in_sizes; (void)n_in; (void)out_size;
    const float* q = (const float*)d_in[0];
    const float* k = (const float*)d_in[1];
    const float* v = (const float*)d_in[2];
    const float* P = (const float*)d_in[3];
    float* out = (float*)d_out;

    cudaFuncSetAttribute(k1_mma, cudaFuncAttributeMaxDynamicSharedMemorySize, K1_SMEM);
    cudaFuncSetAttribute(k2_out, cudaFuncAttributeMaxDynamicSharedMemorySize, K2_SMEM);

    k_prep_P<<<32, 256>>>(P);
    k_prep_v<<<BH_*128, 256>>>(v);
    k1_mma<<<BH_*CH2, NT, K1_SMEM>>>(k);
    k_reduce<<<288, 256>>>();
    k2_out<<<BH_*CH2, NT, K2_SMEM>>>(q, out);
}